// round 2
// baseline (speedup 1.0000x reference)
#include <cuda_runtime.h>

#define NN 50000
#define EE 800000
#define DD 64
#define HH 128
#define BM 128
#define TPB 256

// ---- device-global scratch (no allocations allowed) ----
__device__ float g_agg[NN * DD];     // scatter-mean accumulator
__device__ float g_inv[NN];          // 1 / max(cnt,1)
__device__ int   g_cnt[NN];
__device__ float g_Wc[HH * HH];      // combined We1 (rows 0:64 + 64:128 folded)
__device__ int   g_is64;             // edge_index dtype flag

__device__ __forceinline__ int load_row(const void* eidx, int i) {
    if (g_is64) return (int)((const long long*)eidx)[i];
    return ((const int*)eidx)[i];
}

// Detect whether edge_index is int64 or int32 (JAX x64 may be disabled).
__global__ void detect_kernel(const void* eidx) {
    if (threadIdx.x == 0 && blockIdx.x == 0) {
        const long long* p = (const long long*)eidx;
        int ok = 1;
        for (int i = 0; i < 64; i++) {
            long long v = p[i];
            if (v < 0 || v >= NN) { ok = 0; break; }
        }
        g_is64 = ok;
    }
}

// Wc[k][n] = We1[k][n] + We1[k+64][n] (k<64) ; We1[k+64][n] (64<=k<128)
__global__ void combine_w_k(const float* __restrict__ We1, float* __restrict__ Wc) {
    int i = blockIdx.x * blockDim.x + threadIdx.x;
    if (i < HH * HH) {
        int k = i >> 7, n = i & 127;
        float v = We1[(k + 64) * HH + n];
        if (k < 64) v += We1[k * HH + n];
        Wc[i] = v;
    }
}

__global__ void zero_f4(float* p, int n4) {
    int i = blockIdx.x * blockDim.x + threadIdx.x;
    if (i < n4) ((float4*)p)[i] = make_float4(0.f, 0.f, 0.f, 0.f);
}

__global__ void zero_i_k(int* p, int n) {
    int i = blockIdx.x * blockDim.x + threadIdx.x;
    if (i < n) p[i] = 0;
}

__global__ void count_k(const void* eidx, int* cnt) {
    int i = blockIdx.x * blockDim.x + threadIdx.x;
    if (i < EE) atomicAdd(&cnt[load_row(eidx, i)], 1);
}

__global__ void inv_k(const int* __restrict__ cnt, float* __restrict__ inv) {
    int i = blockIdx.x * blockDim.x + threadIdx.x;
    if (i < NN) inv[i] = 1.0f / fmaxf((float)cnt[i], 1.0f);
}

// ---- shared memory layout (floats) ----
// sAT : A tile transposed [k=128][m=128]            (64 KB)
// sBH : W1 [k][n] stride 132, then reused as H[m][k] stride 132 (66 KB)
// sW2 : W2 [128][64]                                 (32 KB)
// sb1[128], sb2[64], rows[128](ints)
#define S_AT 0
#define S_BH (S_AT + 128 * 128)
#define S_W2 (S_BH + 128 * 132)
#define S_B1 (S_W2 + 128 * 64)
#define S_B2 (S_B1 + 128)
#define S_RW (S_B2 + 64)
#define S_TOT (S_RW + 128)
#define SMEM_BYTES (S_TOT * 4)

// Fused 2-layer MLP over 128-row tiles.
// EDGE:  A = [x[row[e]], edge_attr[e]]  -> W1(=Wc) relu -> W2 ; epilogue:
//        atomicAdd(agg[row], e_new); dst = edge_attr + e_new
// !EDGE: A = [x[i], agg[i]*inv[i]]      -> Wn1 relu -> Wn2 ; dst = x + x_new
template <bool EDGE>
__global__ void __launch_bounds__(TPB, 1)
fused_mlp(const float* x_src,
          const float* a_src,
          const void* __restrict__ eidx,
          const float* __restrict__ W1,
          const float* __restrict__ b1,
          const float* __restrict__ W2,
          const float* __restrict__ b2,
          float* dst,
          float* agg,
          const float* __restrict__ inv,
          int count)
{
    extern __shared__ float sm[];
    float* sAT = sm + S_AT;
    float* sBH = sm + S_BH;
    float* sW2 = sm + S_W2;
    float* sb1 = sm + S_B1;
    float* sb2 = sm + S_B2;
    int*   rws = (int*)(sm + S_RW);

    const int tid = threadIdx.x;
    const int tx = tid & 15;        // n direction
    const int ty = tid >> 4;        // m direction (0..15)
    const int m0a = 4 * ty, m0b = 64 + 4 * ty;
    const int n0a = 4 * tx, n0b = 64 + 4 * tx;
    const int i0 = blockIdx.x * BM;

    // ---- load weights / biases / row indices ----
    #pragma unroll
    for (int i = tid; i < 128 * 32; i += TPB) {
        int r = i >> 5, c4 = (i & 31) << 2;
        float4 v = *(const float4*)&W1[r * 128 + c4];
        *(float4*)&sBH[r * 132 + c4] = v;
    }
    #pragma unroll
    for (int i = tid; i < 128 * 16; i += TPB) {
        int r = i >> 4, c4 = (i & 15) << 2;
        *(float4*)&sW2[r * 64 + c4] = *(const float4*)&W2[r * 64 + c4];
    }
    if (tid < 128) sb1[tid] = b1[tid];
    if (tid < 64)  sb2[tid] = b2[tid];
    if (EDGE) {
        if (tid < 128) rws[tid] = load_row(eidx, i0 + tid);
    }
    __syncthreads();

    // ---- assemble A tile transposed: sAT[k][m] ----
    {
        int m = tid & 127;
        int sel = tid >> 7;                 // 0: x half (k 0..63), 1: attr/agg half
        bool valid = (i0 + m) < count;      // edge grid is exact; node has a tail
        const float* srcrow;
        float scale = 1.0f;
        if (sel == 0) {
            int node = EDGE ? (valid ? rws[m] : 0) : (i0 + m);
            srcrow = x_src + (size_t)(valid ? node : 0) * DD;
        } else {
            srcrow = a_src + (size_t)(valid ? (i0 + m) : 0) * DD;
            if (!EDGE) scale = valid ? inv[i0 + m] : 0.0f;
        }
        #pragma unroll
        for (int it = 0; it < 16; it++) {
            float4 v = make_float4(0.f, 0.f, 0.f, 0.f);
            if (valid) v = *(const float4*)&srcrow[it * 4];
            if (!EDGE && sel == 1) { v.x *= scale; v.y *= scale; v.z *= scale; v.w *= scale; }
            int kb = sel * 64 + it * 4;
            sAT[(kb + 0) * BM + m] = v.x;
            sAT[(kb + 1) * BM + m] = v.y;
            sAT[(kb + 2) * BM + m] = v.z;
            sAT[(kb + 3) * BM + m] = v.w;
        }
    }
    __syncthreads();

    // ---- GEMM1: H = relu(A @ W1 + b1), 8x8 per thread ----
    float acc[8][8];
    #pragma unroll
    for (int i = 0; i < 8; i++)
        #pragma unroll
        for (int j = 0; j < 8; j++) acc[i][j] = 0.0f;

    #pragma unroll 8
    for (int k = 0; k < 128; k++) {
        float a[8], b[8];
        *(float4*)&a[0] = *(float4*)&sAT[k * BM + m0a];
        *(float4*)&a[4] = *(float4*)&sAT[k * BM + m0b];
        *(float4*)&b[0] = *(float4*)&sBH[k * 132 + n0a];
        *(float4*)&b[4] = *(float4*)&sBH[k * 132 + n0b];
        #pragma unroll
        for (int i = 0; i < 8; i++)
            #pragma unroll
            for (int j = 0; j < 8; j++)
                acc[i][j] += a[i] * b[j];
    }
    __syncthreads();   // everyone done reading W1 -> reuse sBH for H[m][k]

    #pragma unroll
    for (int i = 0; i < 8; i++) {
        int m = (i < 4) ? (m0a + i) : (m0b + i - 4);
        float4 h0, h1;
        h0.x = fmaxf(acc[i][0] + sb1[n0a + 0], 0.f);
        h0.y = fmaxf(acc[i][1] + sb1[n0a + 1], 0.f);
        h0.z = fmaxf(acc[i][2] + sb1[n0a + 2], 0.f);
        h0.w = fmaxf(acc[i][3] + sb1[n0a + 3], 0.f);
        h1.x = fmaxf(acc[i][4] + sb1[n0b + 0], 0.f);
        h1.y = fmaxf(acc[i][5] + sb1[n0b + 1], 0.f);
        h1.z = fmaxf(acc[i][6] + sb1[n0b + 2], 0.f);
        h1.w = fmaxf(acc[i][7] + sb1[n0b + 3], 0.f);
        *(float4*)&sBH[m * 132 + n0a] = h0;
        *(float4*)&sBH[m * 132 + n0b] = h1;
    }
    __syncthreads();

    // ---- GEMM2: out = H @ W2, 8x4 per thread (out width 64) ----
    float acc2[8][4];
    #pragma unroll
    for (int i = 0; i < 8; i++)
        #pragma unroll
        for (int j = 0; j < 4; j++) acc2[i][j] = 0.0f;

    #pragma unroll 8
    for (int k = 0; k < 128; k++) {
        float4 b = *(float4*)&sW2[k * 64 + n0a];
        #pragma unroll
        for (int i = 0; i < 8; i++) {
            int m = (i < 4) ? (m0a + i) : (m0b + i - 4);
            float av = sBH[m * 132 + k];
            acc2[i][0] += av * b.x;
            acc2[i][1] += av * b.y;
            acc2[i][2] += av * b.z;
            acc2[i][3] += av * b.w;
        }
    }

    // ---- epilogue ----
    #pragma unroll
    for (int i = 0; i < 8; i++) {
        int ml = (i < 4) ? (m0a + i) : (m0b + i - 4);
        int gi = i0 + ml;
        if (gi >= count) continue;
        float v0 = acc2[i][0] + sb2[n0a + 0];
        float v1 = acc2[i][1] + sb2[n0a + 1];
        float v2 = acc2[i][2] + sb2[n0a + 2];
        float v3 = acc2[i][3] + sb2[n0a + 3];
        float4 o;
        if (EDGE) {
            int r = rws[ml];
            float* ag = agg + (size_t)r * DD + n0a;
            atomicAdd(ag + 0, v0);
            atomicAdd(ag + 1, v1);
            atomicAdd(ag + 2, v2);
            atomicAdd(ag + 3, v3);
            o.x = sAT[(64 + n0a + 0) * BM + ml] + v0;   // edge_attr residual
            o.y = sAT[(64 + n0a + 1) * BM + ml] + v1;
            o.z = sAT[(64 + n0a + 2) * BM + ml] + v2;
            o.w = sAT[(64 + n0a + 3) * BM + ml] + v3;
        } else {
            o.x = sAT[(n0a + 0) * BM + ml] + v0;        // x residual
            o.y = sAT[(n0a + 1) * BM + ml] + v1;
            o.z = sAT[(n0a + 2) * BM + ml] + v2;
            o.w = sAT[(n0a + 3) * BM + ml] + v3;
        }
        *(float4*)&dst[(size_t)gi * DD + n0a] = o;
    }
}

extern "C" void kernel_launch(void* const* d_in, const int* in_sizes, int n_in,
                              void* d_out, int out_size)
{
    const float* x   = (const float*)d_in[0];
    const float* ea  = (const float*)d_in[1];
    const float* We1 = (const float*)d_in[2];
    const float* be1 = (const float*)d_in[3];
    const float* We2 = (const float*)d_in[4];
    const float* be2 = (const float*)d_in[5];
    const float* Wn1 = (const float*)d_in[6];
    const float* bn1 = (const float*)d_in[7];
    const float* Wn2 = (const float*)d_in[8];
    const float* bn2 = (const float*)d_in[9];
    const void*  eidx = d_in[10];

    float* out_x  = (float*)d_out;
    float* out_ea = (float*)d_out + (size_t)NN * DD;

    float *agg, *inv, *Wc;
    int* cnt;
    cudaGetSymbolAddress((void**)&agg, g_agg);
    cudaGetSymbolAddress((void**)&inv, g_inv);
    cudaGetSymbolAddress((void**)&cnt, g_cnt);
    cudaGetSymbolAddress((void**)&Wc,  g_Wc);

    cudaFuncSetAttribute(fused_mlp<true>,  cudaFuncAttributeMaxDynamicSharedMemorySize, SMEM_BYTES);
    cudaFuncSetAttribute(fused_mlp<false>, cudaFuncAttributeMaxDynamicSharedMemorySize, SMEM_BYTES);

    detect_kernel<<<1, 32>>>(eidx);
    combine_w_k<<<(HH * HH + 255) / 256, 256>>>(We1, Wc);
    zero_i_k<<<(NN + 255) / 256, 256>>>(cnt, NN);
    count_k<<<(EE + 255) / 256, 256>>>(eidx, cnt);
    inv_k<<<(NN + 255) / 256, 256>>>(cnt, inv);

    const float* xs = x;
    const float* es = ea;
    for (int it = 0; it < 2; it++) {
        zero_f4<<<(NN * DD / 4 + 255) / 256, 256>>>(agg, NN * DD / 4);
        fused_mlp<true><<<EE / BM, TPB, SMEM_BYTES>>>(
            xs, es, eidx, Wc, be1, We2, be2, out_ea, agg, nullptr, EE);
        fused_mlp<false><<<(NN + BM - 1) / BM, TPB, SMEM_BYTES>>>(
            xs, agg, nullptr, Wn1, bn1, Wn2, bn2, out_x, nullptr, inv, NN);
        xs = out_x;
        es = out_ea;
    }
}

// round 4
// speedup vs baseline: 1.9860x; 1.9860x over previous
#include <cuda_runtime.h>
#include <cuda_bf16.h>
#include <cstdint>

#define NN 50000
#define EE 800000
#define DD 64
#define ET 6250                 // EE / 128
#define NT 391                  // ceil(NN / 128)
#define KP 136                  // padded K stride (bf16 elements)

// ---------------- device-global scratch (no allocations allowed) ----------
__device__ float g_agg[NN * DD];
__device__ float g_inv[NN];
__device__ int   g_cnt[NN];
__device__ float g_Wc[128 * 128];
__device__ int   g_is64;

__device__ __forceinline__ int load_row(const void* eidx, int i) {
    if (g_is64) return (int)((const long long*)eidx)[i];
    return ((const int*)eidx)[i];
}

__global__ void detect_kernel(const void* eidx) {
    if (threadIdx.x == 0 && blockIdx.x == 0) {
        const long long* p = (const long long*)eidx;
        int ok = 1;
        for (int i = 0; i < 64; i++) {
            long long v = p[i];
            if (v < 0 || v >= NN) { ok = 0; break; }
        }
        g_is64 = ok;
    }
}

__global__ void combine_w_k(const float* __restrict__ We1, float* __restrict__ Wc) {
    int i = blockIdx.x * blockDim.x + threadIdx.x;
    if (i < 128 * 128) {
        int k = i >> 7, n = i & 127;
        float v = We1[(k + 64) * 128 + n];
        if (k < 64) v += We1[k * 128 + n];
        Wc[i] = v;
    }
}

__global__ void zero_f4(float* p, int n4) {
    int i = blockIdx.x * blockDim.x + threadIdx.x;
    if (i < n4) ((float4*)p)[i] = make_float4(0.f, 0.f, 0.f, 0.f);
}
__global__ void zero_i_k(int* p, int n) {
    int i = blockIdx.x * blockDim.x + threadIdx.x;
    if (i < n) p[i] = 0;
}
__global__ void count_k(const void* eidx, int* cnt) {
    int i = blockIdx.x * blockDim.x + threadIdx.x;
    if (i < EE) atomicAdd(&cnt[load_row(eidx, i)], 1);
}
__global__ void inv_k(const int* __restrict__ cnt, float* __restrict__ inv) {
    int i = blockIdx.x * blockDim.x + threadIdx.x;
    if (i < NN) inv[i] = 1.0f / fmaxf((float)cnt[i], 1.0f);
}

// ---------------- helpers ---------------------------------------------------
__device__ __forceinline__ uint32_t pack_bf2(__nv_bfloat16 a, __nv_bfloat16 b) {
    unsigned short ua = *(unsigned short*)&a, ub = *(unsigned short*)&b;
    return (uint32_t)ua | ((uint32_t)ub << 16);
}

// fp32 pair -> bf16 hi-pair + bf16 lo-pair (split-2)
__device__ __forceinline__ void split_pair(float f0, float f1, uint32_t& hi, uint32_t& lo) {
    __nv_bfloat16 h0 = __float2bfloat16_rn(f0);
    __nv_bfloat16 h1 = __float2bfloat16_rn(f1);
    float r0 = f0 - __bfloat162float(h0);
    float r1 = f1 - __bfloat162float(h1);
    hi = pack_bf2(h0, h1);
    lo = pack_bf2(__float2bfloat16_rn(r0), __float2bfloat16_rn(r1));
}

// m16n8k16 row.col bf16 -> f32 accumulate (baseline PTX, sm_80+)
__device__ __forceinline__ void mma_bf16(float* d, const uint32_t* a, const uint32_t* b) {
    asm volatile(
        "mma.sync.aligned.m16n8k16.row.col.f32.bf16.bf16.f32 "
        "{%0,%1,%2,%3}, {%4,%5,%6,%7}, {%8,%9}, {%0,%1,%2,%3};"
        : "+f"(d[0]), "+f"(d[1]), "+f"(d[2]), "+f"(d[3])
        : "r"(a[0]), "r"(a[1]), "r"(a[2]), "r"(a[3]), "r"(b[0]), "r"(b[1]));
}

// ---------------- SMEM layout (bytes) --------------------------------------
#define OFF_AH   0                 // A tile hi  [128][KP] bf16 (also H hi)
#define OFF_AL   34816             // A tile lo
#define OFF_W1H  69632             // W1^T hi    [n=128][KP]
#define OFF_W1L  104448
#define OFF_W2H  139264            // W2^T hi    [n=64][KP]
#define OFF_W2L  156672
#define OFF_B1   174080            // 128 f32
#define OFF_B2   174592            // 64 f32
#define OFF_RW   174848            // 128 int rows
#define SMEMSZ   175360

// Fused 2-layer MLP on HMMA (mma.sync) with bf16 split-2, persistent CTAs.
// EDGE:  A = [x[row[e]] | edge_attr[e]] -> W1(=Wc) relu -> W2;
//        epilogue: red.add agg[row] += e_new ; dst = edge_attr + e_new
// !EDGE: A = [x[i] | agg[i]*inv[i]] -> Wn1 relu -> Wn2 ; dst = x + x_new
template <bool EDGE>
__global__ void __launch_bounds__(256, 1)
gnn_mma(const float* __restrict__ x_src, const float* __restrict__ a_src,
        const void* __restrict__ eidx,
        const float* __restrict__ W1, const float* __restrict__ b1,
        const float* __restrict__ W2, const float* __restrict__ b2,
        float* __restrict__ dst, float* __restrict__ agg,
        const float* __restrict__ inv, int ntiles, int count)
{
    extern __shared__ char smc[];
    uint16_t* sAh  = (uint16_t*)(smc + OFF_AH);
    uint16_t* sAl  = (uint16_t*)(smc + OFF_AL);
    uint16_t* sW1h = (uint16_t*)(smc + OFF_W1H);
    uint16_t* sW1l = (uint16_t*)(smc + OFF_W1L);
    uint16_t* sW2h = (uint16_t*)(smc + OFF_W2H);
    uint16_t* sW2l = (uint16_t*)(smc + OFF_W2L);
    float*    sb1  = (float*)(smc + OFF_B1);
    float*    sb2  = (float*)(smc + OFF_B2);
    int*      sRows = (int*)(smc + OFF_RW);

    const int tid = threadIdx.x;
    const int lane = tid & 31, w = tid >> 5;
    const int g = lane >> 2, qt = lane & 3;
    const int wm = w >> 1, wn = w & 1;

    // ---- stage split-transposed weights once (persistent CTA) ----
    {
        int n = tid & 127, k0 = (tid >> 7) * 64;
        for (int k = k0; k < k0 + 64; k += 2) {
            uint32_t hi, lo;
            split_pair(W1[k * 128 + n], W1[(k + 1) * 128 + n], hi, lo);
            *(uint32_t*)&sW1h[n * KP + k] = hi;
            *(uint32_t*)&sW1l[n * KP + k] = lo;
        }
    }
    {
        int n = tid & 63, k0 = (tid >> 6) * 32;
        for (int k = k0; k < k0 + 32; k += 2) {
            uint32_t hi, lo;
            split_pair(W2[k * 64 + n], W2[(k + 1) * 64 + n], hi, lo);
            *(uint32_t*)&sW2h[n * KP + k] = hi;
            *(uint32_t*)&sW2l[n * KP + k] = lo;
        }
    }
    if (tid < 128) sb1[tid] = b1[tid];
    if (tid < 64)  sb2[tid] = b2[tid];
    __syncthreads();

    for (int tile = blockIdx.x; tile < ntiles; tile += gridDim.x) {
        const int i0 = tile * 128;

        if (EDGE) {
            if (tid < 128) sRows[tid] = load_row(eidx, i0 + tid);
            __syncthreads();
        }

        // ---- build A tile (bf16 split, row-major [m][KP]) ----
        {
            const int m = tid & 127, half = tid >> 7;
            const int gi = i0 + m;
            const bool valid = EDGE || (gi < count);
            const float* src;
            float scale = 1.0f;
            bool doscale = false;
            if (half == 0) {
                int node = EDGE ? sRows[m] : (valid ? gi : 0);
                src = x_src + (size_t)node * DD;
            } else {
                src = a_src + (size_t)(valid ? gi : 0) * DD;
                if (!EDGE) { scale = valid ? inv[gi] : 0.0f; doscale = true; }
            }
            #pragma unroll
            for (int c = 0; c < 64; c += 8) {
                float4 f0 = *(const float4*)(src + c);
                float4 f1 = *(const float4*)(src + c + 4);
                if (doscale) {
                    f0.x *= scale; f0.y *= scale; f0.z *= scale; f0.w *= scale;
                    f1.x *= scale; f1.y *= scale; f1.z *= scale; f1.w *= scale;
                }
                uint32_t hw[4], lw[4];
                split_pair(f0.x, f0.y, hw[0], lw[0]);
                split_pair(f0.z, f0.w, hw[1], lw[1]);
                split_pair(f1.x, f1.y, hw[2], lw[2]);
                split_pair(f1.z, f1.w, hw[3], lw[3]);
                int e = m * KP + half * 64 + c;
                *(uint4*)&sAh[e] = *(uint4*)hw;
                *(uint4*)&sAl[e] = *(uint4*)lw;
            }
        }
        __syncthreads();

        // ---- GEMM1: D1 = A @ W1 (3 split terms), warp tile 32x64 ----
        float acc[2][8][4];
        #pragma unroll
        for (int mt = 0; mt < 2; mt++)
            #pragma unroll
            for (int nt = 0; nt < 8; nt++)
                #pragma unroll
                for (int j = 0; j < 4; j++) acc[mt][nt][j] = 0.f;

        #pragma unroll
        for (int t = 0; t < 3; t++) {
            const uint16_t* As = (t == 2) ? sAl : sAh;
            const uint16_t* Bs = (t == 1) ? sW1l : sW1h;
            #pragma unroll
            for (int ks = 0; ks < 8; ks++) {
                const int kb = ks * 16 + 2 * qt;
                uint32_t a[2][4];
                #pragma unroll
                for (int mt = 0; mt < 2; mt++) {
                    int e = (wm * 32 + mt * 16 + g) * KP + kb;
                    a[mt][0] = *(const uint32_t*)&As[e];
                    a[mt][1] = *(const uint32_t*)&As[e + 8 * KP];
                    a[mt][2] = *(const uint32_t*)&As[e + 8];
                    a[mt][3] = *(const uint32_t*)&As[e + 8 * KP + 8];
                }
                #pragma unroll
                for (int nt = 0; nt < 8; nt++) {
                    int e = (wn * 64 + nt * 8 + g) * KP + kb;
                    uint32_t bf[2];
                    bf[0] = *(const uint32_t*)&Bs[e];
                    bf[1] = *(const uint32_t*)&Bs[e + 8];
                    mma_bf16(acc[0][nt], a[0], bf);
                    mma_bf16(acc[1][nt], a[1], bf);
                }
            }
        }
        __syncthreads();   // all A reads done -> safe to overwrite with H

        // ---- H = relu(D1 + b1) -> split back into A buffers ----
        #pragma unroll
        for (int mt = 0; mt < 2; mt++)
            #pragma unroll
            for (int nt = 0; nt < 8; nt++) {
                int row = wm * 32 + mt * 16 + g;
                int col = wn * 64 + nt * 8 + 2 * qt;
                float v0 = fmaxf(acc[mt][nt][0] + sb1[col], 0.f);
                float v1 = fmaxf(acc[mt][nt][1] + sb1[col + 1], 0.f);
                float v2 = fmaxf(acc[mt][nt][2] + sb1[col], 0.f);
                float v3 = fmaxf(acc[mt][nt][3] + sb1[col + 1], 0.f);
                uint32_t hi, lo;
                split_pair(v0, v1, hi, lo);
                *(uint32_t*)&sAh[row * KP + col] = hi;
                *(uint32_t*)&sAl[row * KP + col] = lo;
                split_pair(v2, v3, hi, lo);
                *(uint32_t*)&sAh[(row + 8) * KP + col] = hi;
                *(uint32_t*)&sAl[(row + 8) * KP + col] = lo;
            }
        __syncthreads();

        // ---- GEMM2: D2 = H @ W2 (3 split terms), warp tile 32x32 ----
        float acc2[2][4][4];
        #pragma unroll
        for (int mt = 0; mt < 2; mt++)
            #pragma unroll
            for (int nt = 0; nt < 4; nt++)
                #pragma unroll
                for (int j = 0; j < 4; j++) acc2[mt][nt][j] = 0.f;

        #pragma unroll
        for (int t = 0; t < 3; t++) {
            const uint16_t* As = (t == 2) ? sAl : sAh;
            const uint16_t* Bs = (t == 1) ? sW2l : sW2h;
            #pragma unroll
            for (int ks = 0; ks < 8; ks++) {
                const int kb = ks * 16 + 2 * qt;
                uint32_t a[2][4];
                #pragma unroll
                for (int mt = 0; mt < 2; mt++) {
                    int e = (wm * 32 + mt * 16 + g) * KP + kb;
                    a[mt][0] = *(const uint32_t*)&As[e];
                    a[mt][1] = *(const uint32_t*)&As[e + 8 * KP];
                    a[mt][2] = *(const uint32_t*)&As[e + 8];
                    a[mt][3] = *(const uint32_t*)&As[e + 8 * KP + 8];
                }
                #pragma unroll
                for (int nt = 0; nt < 4; nt++) {
                    int e = (wn * 32 + nt * 8 + g) * KP + kb;
                    uint32_t bf[2];
                    bf[0] = *(const uint32_t*)&Bs[e];
                    bf[1] = *(const uint32_t*)&Bs[e + 8];
                    mma_bf16(acc2[0][nt], a[0], bf);
                    mma_bf16(acc2[1][nt], a[1], bf);
                }
            }
        }

        // ---- epilogue: out = residual + (D2 + b2); EDGE also scatter-add ----
        {
            const float* res = EDGE ? a_src : x_src;
            #pragma unroll
            for (int mt = 0; mt < 2; mt++)
                #pragma unroll
                for (int nt = 0; nt < 4; nt++) {
                    int rl = wm * 32 + mt * 16 + g;
                    int col = wn * 32 + nt * 8 + 2 * qt;
                    #pragma unroll
                    for (int rh = 0; rh < 2; rh++) {
                        int row = rl + rh * 8;
                        int gi = i0 + row;
                        if (!EDGE && gi >= count) continue;
                        float vx = acc2[mt][nt][rh * 2 + 0] + sb2[col];
                        float vy = acc2[mt][nt][rh * 2 + 1] + sb2[col + 1];
                        if (EDGE) {
                            float* ap = agg + (size_t)sRows[row] * DD + col;
                            asm volatile("red.global.add.v2.f32 [%0], {%1, %2};"
                                         :: "l"(ap), "f"(vx), "f"(vy) : "memory");
                        }
                        float2 rv = *(const float2*)(res + (size_t)gi * DD + col);
                        float2 ov = make_float2(rv.x + vx, rv.y + vy);
                        *(float2*)(dst + (size_t)gi * DD + col) = ov;
                    }
                }
        }
        __syncthreads();
    }
}

extern "C" void kernel_launch(void* const* d_in, const int* in_sizes, int n_in,
                              void* d_out, int out_size)
{
    const float* x   = (const float*)d_in[0];
    const float* ea  = (const float*)d_in[1];
    const float* We1 = (const float*)d_in[2];
    const float* be1 = (const float*)d_in[3];
    const float* We2 = (const float*)d_in[4];
    const float* be2 = (const float*)d_in[5];
    const float* Wn1 = (const float*)d_in[6];
    const float* bn1 = (const float*)d_in[7];
    const float* Wn2 = (const float*)d_in[8];
    const float* bn2 = (const float*)d_in[9];
    const void*  eidx = d_in[10];

    float* out_x  = (float*)d_out;
    float* out_ea = (float*)d_out + (size_t)NN * DD;

    float *agg, *inv, *Wc;
    int* cnt;
    cudaGetSymbolAddress((void**)&agg, g_agg);
    cudaGetSymbolAddress((void**)&inv, g_inv);
    cudaGetSymbolAddress((void**)&cnt, g_cnt);
    cudaGetSymbolAddress((void**)&Wc,  g_Wc);

    cudaFuncSetAttribute(gnn_mma<true>,  cudaFuncAttributeMaxDynamicSharedMemorySize, SMEMSZ);
    cudaFuncSetAttribute(gnn_mma<false>, cudaFuncAttributeMaxDynamicSharedMemorySize, SMEMSZ);

    int smcount = 148;
    cudaDeviceGetAttribute(&smcount, cudaDevAttrMultiProcessorCount, 0);
    int ge = smcount < ET ? smcount : ET;
    int gn = smcount < NT ? smcount : NT;

    detect_kernel<<<1, 32>>>(eidx);
    combine_w_k<<<(128 * 128 + 255) / 256, 256>>>(We1, Wc);
    zero_i_k<<<(NN + 255) / 256, 256>>>(cnt, NN);
    count_k<<<(EE + 255) / 256, 256>>>(eidx, cnt);
    inv_k<<<(NN + 255) / 256, 256>>>(cnt, inv);

    const float* xs = x;
    const float* es = ea;
    for (int it = 0; it < 2; it++) {
        zero_f4<<<(NN * DD / 4 + 255) / 256, 256>>>(agg, NN * DD / 4);
        gnn_mma<true><<<ge, 256, SMEMSZ>>>(
            xs, es, eidx, Wc, be1, We2, be2, out_ea, agg, nullptr, ET, EE);
        gnn_mma<false><<<gn, 256, SMEMSZ>>>(
            xs, agg, nullptr, Wn1, bn1, Wn2, bn2, out_x, nullptr, inv, NT, NN);
        xs = out_x;
        es = out_ea;
    }
}

// round 5
// speedup vs baseline: 2.0563x; 1.0354x over previous
#include <cuda_runtime.h>
#include <cuda_bf16.h>
#include <cstdint>

#define NN 50000
#define EE 800000
#define DD 64
#define ET 6250                 // EE / 128
#define NT 391                  // ceil(NN / 128)
#define KP 136                  // padded K stride (bf16 elements)

// ---------------- device-global scratch (no allocations allowed) ----------
__device__ float g_agg[NN * DD];
__device__ float g_inv[NN];
__device__ int   g_cnt[NN];
__device__ float g_Wc[128 * 128];
__device__ int   g_is64;

__device__ __forceinline__ int load_row(const void* eidx, int i) {
    if (g_is64) return (int)((const long long*)eidx)[i];
    return ((const int*)eidx)[i];
}

// detect dtype (block 0, thread 0) + zero cnt (whole grid) in ONE kernel so the
// edge kernel is the 6th launch (ncu -s 5 -c 1 captures it).
__global__ void detect_zero_k(const void* eidx, int* cnt) {
    int i = blockIdx.x * blockDim.x + threadIdx.x;
    if (i < NN) cnt[i] = 0;
    if (i == 0) {
        const long long* p = (const long long*)eidx;
        int ok = 1;
        for (int j = 0; j < 64; j++) {
            long long v = p[j];
            if (v < 0 || v >= NN) { ok = 0; break; }
        }
        g_is64 = ok;
    }
}

__global__ void combine_w_k(const float* __restrict__ We1, float* __restrict__ Wc) {
    int i = blockIdx.x * blockDim.x + threadIdx.x;
    if (i < 128 * 128) {
        int k = i >> 7, n = i & 127;
        float v = We1[(k + 64) * 128 + n];
        if (k < 64) v += We1[k * 128 + n];
        Wc[i] = v;
    }
}

__global__ void zero_f4(float* p, int n4) {
    int i = blockIdx.x * blockDim.x + threadIdx.x;
    if (i < n4) ((float4*)p)[i] = make_float4(0.f, 0.f, 0.f, 0.f);
}
__global__ void count_k(const void* eidx, int* cnt) {
    int i = blockIdx.x * blockDim.x + threadIdx.x;
    if (i < EE) atomicAdd(&cnt[load_row(eidx, i)], 1);
}
__global__ void inv_k(const int* __restrict__ cnt, float* __restrict__ inv) {
    int i = blockIdx.x * blockDim.x + threadIdx.x;
    if (i < NN) inv[i] = 1.0f / fmaxf((float)cnt[i], 1.0f);
}

// ---------------- helpers ---------------------------------------------------
__device__ __forceinline__ uint32_t pack_bf2(__nv_bfloat16 a, __nv_bfloat16 b) {
    unsigned short ua = *(unsigned short*)&a, ub = *(unsigned short*)&b;
    return (uint32_t)ua | ((uint32_t)ub << 16);
}

__device__ __forceinline__ void split_pair(float f0, float f1, uint32_t& hi, uint32_t& lo) {
    __nv_bfloat16 h0 = __float2bfloat16_rn(f0);
    __nv_bfloat16 h1 = __float2bfloat16_rn(f1);
    float r0 = f0 - __bfloat162float(h0);
    float r1 = f1 - __bfloat162float(h1);
    hi = pack_bf2(h0, h1);
    lo = pack_bf2(__float2bfloat16_rn(r0), __float2bfloat16_rn(r1));
}

// m16n8k16 row.col bf16 -> f32 accumulate (baseline PTX, sm_80+)
__device__ __forceinline__ void mma_bf16(float* d, const uint32_t* a, const uint32_t* b) {
    asm volatile(
        "mma.sync.aligned.m16n8k16.row.col.f32.bf16.bf16.f32 "
        "{%0,%1,%2,%3}, {%4,%5,%6,%7}, {%8,%9}, {%0,%1,%2,%3};"
        : "+f"(d[0]), "+f"(d[1]), "+f"(d[2]), "+f"(d[3])
        : "r"(a[0]), "r"(a[1]), "r"(a[2]), "r"(a[3]), "r"(b[0]), "r"(b[1]));
}

// ---------------- SMEM layout (bytes) --------------------------------------
#define OFF_AH   0                 // A tile hi  [128][KP] bf16 (also H hi)
#define OFF_AL   34816             // A tile lo
#define OFF_W1H  69632             // W1^T hi    [n=128][KP]
#define OFF_W1L  104448
#define OFF_W2H  139264            // W2^T hi    [n=64][KP]
#define OFF_W2L  156672
#define OFF_B1   174080            // 128 f32
#define OFF_B2   174592            // 64 f32
#define OFF_RW   174848            // 128 int rows
#define SMEMSZ   175360

// Fused 2-layer MLP on HMMA with bf16 split-2 (3 MMA terms), persistent CTAs.
// Fragment-reuse inner loop: a_hi/a_lo/b_hi/b_lo each loaded ONCE per (ks[,nt]).
template <bool EDGE>
__global__ void __launch_bounds__(256, 1)
gnn_mma(const float* __restrict__ x_src, const float* __restrict__ a_src,
        const void* __restrict__ eidx,
        const float* __restrict__ W1, const float* __restrict__ b1,
        const float* __restrict__ W2, const float* __restrict__ b2,
        float* __restrict__ dst, float* __restrict__ agg,
        const float* __restrict__ inv, int ntiles, int count)
{
    extern __shared__ char smc[];
    uint16_t* sAh  = (uint16_t*)(smc + OFF_AH);
    uint16_t* sAl  = (uint16_t*)(smc + OFF_AL);
    uint16_t* sW1h = (uint16_t*)(smc + OFF_W1H);
    uint16_t* sW1l = (uint16_t*)(smc + OFF_W1L);
    uint16_t* sW2h = (uint16_t*)(smc + OFF_W2H);
    uint16_t* sW2l = (uint16_t*)(smc + OFF_W2L);
    float*    sb1  = (float*)(smc + OFF_B1);
    float*    sb2  = (float*)(smc + OFF_B2);
    int*      sRows = (int*)(smc + OFF_RW);

    const int tid = threadIdx.x;
    const int lane = tid & 31, w = tid >> 5;
    const int g = lane >> 2, qt = lane & 3;
    const int wm = w >> 1, wn = w & 1;

    // ---- stage split-transposed weights once (persistent CTA) ----
    {
        int n = tid & 127, k0 = (tid >> 7) * 64;
        for (int k = k0; k < k0 + 64; k += 2) {
            uint32_t hi, lo;
            split_pair(W1[k * 128 + n], W1[(k + 1) * 128 + n], hi, lo);
            *(uint32_t*)&sW1h[n * KP + k] = hi;
            *(uint32_t*)&sW1l[n * KP + k] = lo;
        }
    }
    {
        int n = tid & 63, k0 = (tid >> 6) * 32;
        for (int k = k0; k < k0 + 32; k += 2) {
            uint32_t hi, lo;
            split_pair(W2[k * 64 + n], W2[(k + 1) * 64 + n], hi, lo);
            *(uint32_t*)&sW2h[n * KP + k] = hi;
            *(uint32_t*)&sW2l[n * KP + k] = lo;
        }
    }
    if (tid < 128) sb1[tid] = b1[tid];
    if (tid < 64)  sb2[tid] = b2[tid];
    __syncthreads();

    for (int tile = blockIdx.x; tile < ntiles; tile += gridDim.x) {
        const int i0 = tile * 128;

        if (EDGE) {
            if (tid < 128) sRows[tid] = load_row(eidx, i0 + tid);
            __syncthreads();
        }

        // ---- build A tile (bf16 split, row-major [m][KP]) ----
        {
            const int m = tid & 127, half = tid >> 7;
            const int gi = i0 + m;
            const bool valid = EDGE || (gi < count);
            const float* src;
            float scale = 1.0f;
            bool doscale = false;
            if (half == 0) {
                int node = EDGE ? sRows[m] : (valid ? gi : 0);
                src = x_src + (size_t)node * DD;
            } else {
                src = a_src + (size_t)(valid ? gi : 0) * DD;
                if (!EDGE) { scale = valid ? inv[gi] : 0.0f; doscale = true; }
            }
            #pragma unroll
            for (int c = 0; c < 64; c += 8) {
                float4 f0 = *(const float4*)(src + c);
                float4 f1 = *(const float4*)(src + c + 4);
                if (doscale) {
                    f0.x *= scale; f0.y *= scale; f0.z *= scale; f0.w *= scale;
                    f1.x *= scale; f1.y *= scale; f1.z *= scale; f1.w *= scale;
                }
                uint32_t hw[4], lw[4];
                split_pair(f0.x, f0.y, hw[0], lw[0]);
                split_pair(f0.z, f0.w, hw[1], lw[1]);
                split_pair(f1.x, f1.y, hw[2], lw[2]);
                split_pair(f1.z, f1.w, hw[3], lw[3]);
                int e = m * KP + half * 64 + c;
                *(uint4*)&sAh[e] = *(uint4*)hw;
                *(uint4*)&sAl[e] = *(uint4*)lw;
            }
        }
        __syncthreads();

        // ---- GEMM1: D1 = A @ W1, 3 split terms, fragment-reuse loop ----
        float acc[2][8][4];
        #pragma unroll
        for (int mt = 0; mt < 2; mt++)
            #pragma unroll
            for (int nt = 0; nt < 8; nt++)
                #pragma unroll
                for (int j = 0; j < 4; j++) acc[mt][nt][j] = 0.f;

        #pragma unroll
        for (int ks = 0; ks < 8; ks++) {
            const int kb = ks * 16 + 2 * qt;
            uint32_t ah[2][4], al[2][4];
            #pragma unroll
            for (int mt = 0; mt < 2; mt++) {
                int e = (wm * 32 + mt * 16 + g) * KP + kb;
                ah[mt][0] = *(const uint32_t*)&sAh[e];
                ah[mt][1] = *(const uint32_t*)&sAh[e + 8 * KP];
                ah[mt][2] = *(const uint32_t*)&sAh[e + 8];
                ah[mt][3] = *(const uint32_t*)&sAh[e + 8 * KP + 8];
                al[mt][0] = *(const uint32_t*)&sAl[e];
                al[mt][1] = *(const uint32_t*)&sAl[e + 8 * KP];
                al[mt][2] = *(const uint32_t*)&sAl[e + 8];
                al[mt][3] = *(const uint32_t*)&sAl[e + 8 * KP + 8];
            }
            #pragma unroll
            for (int nt = 0; nt < 8; nt++) {
                int e = (wn * 64 + nt * 8 + g) * KP + kb;
                uint32_t bh[2], bl[2];
                bh[0] = *(const uint32_t*)&sW1h[e];
                bh[1] = *(const uint32_t*)&sW1h[e + 8];
                bl[0] = *(const uint32_t*)&sW1l[e];
                bl[1] = *(const uint32_t*)&sW1l[e + 8];
                mma_bf16(acc[0][nt], ah[0], bh);
                mma_bf16(acc[1][nt], ah[1], bh);
                mma_bf16(acc[0][nt], ah[0], bl);
                mma_bf16(acc[1][nt], ah[1], bl);
                mma_bf16(acc[0][nt], al[0], bh);
                mma_bf16(acc[1][nt], al[1], bh);
            }
        }
        __syncthreads();   // all A reads done -> safe to overwrite with H

        // ---- H = relu(D1 + b1) -> split back into A buffers ----
        #pragma unroll
        for (int mt = 0; mt < 2; mt++)
            #pragma unroll
            for (int nt = 0; nt < 8; nt++) {
                int row = wm * 32 + mt * 16 + g;
                int col = wn * 64 + nt * 8 + 2 * qt;
                float v0 = fmaxf(acc[mt][nt][0] + sb1[col], 0.f);
                float v1 = fmaxf(acc[mt][nt][1] + sb1[col + 1], 0.f);
                float v2 = fmaxf(acc[mt][nt][2] + sb1[col], 0.f);
                float v3 = fmaxf(acc[mt][nt][3] + sb1[col + 1], 0.f);
                uint32_t hi, lo;
                split_pair(v0, v1, hi, lo);
                *(uint32_t*)&sAh[row * KP + col] = hi;
                *(uint32_t*)&sAl[row * KP + col] = lo;
                split_pair(v2, v3, hi, lo);
                *(uint32_t*)&sAh[(row + 8) * KP + col] = hi;
                *(uint32_t*)&sAl[(row + 8) * KP + col] = lo;
            }
        __syncthreads();

        // ---- GEMM2: D2 = H @ W2, 3 split terms, fragment-reuse loop ----
        float acc2[2][4][4];
        #pragma unroll
        for (int mt = 0; mt < 2; mt++)
            #pragma unroll
            for (int nt = 0; nt < 4; nt++)
                #pragma unroll
                for (int j = 0; j < 4; j++) acc2[mt][nt][j] = 0.f;

        #pragma unroll
        for (int ks = 0; ks < 8; ks++) {
            const int kb = ks * 16 + 2 * qt;
            uint32_t ah[2][4], al[2][4];
            #pragma unroll
            for (int mt = 0; mt < 2; mt++) {
                int e = (wm * 32 + mt * 16 + g) * KP + kb;
                ah[mt][0] = *(const uint32_t*)&sAh[e];
                ah[mt][1] = *(const uint32_t*)&sAh[e + 8 * KP];
                ah[mt][2] = *(const uint32_t*)&sAh[e + 8];
                ah[mt][3] = *(const uint32_t*)&sAh[e + 8 * KP + 8];
                al[mt][0] = *(const uint32_t*)&sAl[e];
                al[mt][1] = *(const uint32_t*)&sAl[e + 8 * KP];
                al[mt][2] = *(const uint32_t*)&sAl[e + 8];
                al[mt][3] = *(const uint32_t*)&sAl[e + 8 * KP + 8];
            }
            #pragma unroll
            for (int nt = 0; nt < 4; nt++) {
                int e = (wn * 32 + nt * 8 + g) * KP + kb;
                uint32_t bh[2], bl[2];
                bh[0] = *(const uint32_t*)&sW2h[e];
                bh[1] = *(const uint32_t*)&sW2h[e + 8];
                bl[0] = *(const uint32_t*)&sW2l[e];
                bl[1] = *(const uint32_t*)&sW2l[e + 8];
                mma_bf16(acc2[0][nt], ah[0], bh);
                mma_bf16(acc2[1][nt], ah[1], bh);
                mma_bf16(acc2[0][nt], ah[0], bl);
                mma_bf16(acc2[1][nt], ah[1], bl);
                mma_bf16(acc2[0][nt], al[0], bh);
                mma_bf16(acc2[1][nt], al[1], bh);
            }
        }

        // ---- epilogue: out = residual + (D2 + b2); EDGE also scatter-add ----
        {
            const float* res = EDGE ? a_src : x_src;
            #pragma unroll
            for (int mt = 0; mt < 2; mt++)
                #pragma unroll
                for (int nt = 0; nt < 4; nt++) {
                    int rl = wm * 32 + mt * 16 + g;
                    int col = wn * 32 + nt * 8 + 2 * qt;
                    #pragma unroll
                    for (int rh = 0; rh < 2; rh++) {
                        int row = rl + rh * 8;
                        int gi = i0 + row;
                        if (!EDGE && gi >= count) continue;
                        float vx = acc2[mt][nt][rh * 2 + 0] + sb2[col];
                        float vy = acc2[mt][nt][rh * 2 + 1] + sb2[col + 1];
                        if (EDGE) {
                            float* ap = agg + (size_t)sRows[row] * DD + col;
                            asm volatile("red.global.add.v2.f32 [%0], {%1, %2};"
                                         :: "l"(ap), "f"(vx), "f"(vy) : "memory");
                        }
                        float2 rv = *(const float2*)(res + (size_t)gi * DD + col);
                        float2 ov = make_float2(rv.x + vx, rv.y + vy);
                        *(float2*)(dst + (size_t)gi * DD + col) = ov;
                    }
                }
        }
        __syncthreads();
    }
}

extern "C" void kernel_launch(void* const* d_in, const int* in_sizes, int n_in,
                              void* d_out, int out_size)
{
    const float* x   = (const float*)d_in[0];
    const float* ea  = (const float*)d_in[1];
    const float* We1 = (const float*)d_in[2];
    const float* be1 = (const float*)d_in[3];
    const float* We2 = (const float*)d_in[4];
    const float* be2 = (const float*)d_in[5];
    const float* Wn1 = (const float*)d_in[6];
    const float* bn1 = (const float*)d_in[7];
    const float* Wn2 = (const float*)d_in[8];
    const float* bn2 = (const float*)d_in[9];
    const void*  eidx = d_in[10];

    float* out_x  = (float*)d_out;
    float* out_ea = (float*)d_out + (size_t)NN * DD;

    float *agg, *inv, *Wc;
    int* cnt;
    cudaGetSymbolAddress((void**)&agg, g_agg);
    cudaGetSymbolAddress((void**)&inv, g_inv);
    cudaGetSymbolAddress((void**)&cnt, g_cnt);
    cudaGetSymbolAddress((void**)&Wc,  g_Wc);

    cudaFuncSetAttribute(gnn_mma<true>,  cudaFuncAttributeMaxDynamicSharedMemorySize, SMEMSZ);
    cudaFuncSetAttribute(gnn_mma<false>, cudaFuncAttributeMaxDynamicSharedMemorySize, SMEMSZ);

    int smcount = 148;
    cudaDeviceGetAttribute(&smcount, cudaDevAttrMultiProcessorCount, 0);
    int ge = smcount < ET ? smcount : ET;
    int gn = smcount < NT ? smcount : NT;

    // Launch order chosen so the FIRST edge gnn_mma is launch #6 (ncu -s 5 -c 1).
    detect_zero_k<<<(NN + 255) / 256, 256>>>(eidx, cnt);            // 1
    combine_w_k<<<(128 * 128 + 255) / 256, 256>>>(We1, Wc);         // 2
    count_k<<<(EE + 255) / 256, 256>>>(eidx, cnt);                  // 3
    inv_k<<<(NN + 255) / 256, 256>>>(cnt, inv);                     // 4

    const float* xs = x;
    const float* es = ea;
    for (int it = 0; it < 2; it++) {
        zero_f4<<<(NN * DD / 4 + 255) / 256, 256>>>(agg, NN * DD / 4);   // 5, 8
        gnn_mma<true><<<ge, 256, SMEMSZ>>>(                              // 6 <- profiled
            xs, es, eidx, Wc, be1, We2, be2, out_ea, agg, nullptr, ET, EE);
        gnn_mma<false><<<gn, 256, SMEMSZ>>>(                             // 7
            xs, agg, nullptr, Wn1, bn1, Wn2, bn2, out_x, nullptr, inv, NT, NN);
        xs = out_x;
        es = out_ea;
    }
}

// round 6
// speedup vs baseline: 2.1793x; 1.0598x over previous
#include <cuda_runtime.h>
#include <cuda_bf16.h>
#include <cstdint>

#define NN 50000
#define EE 800000
#define DD 64
#define ET 6250                 // EE / 128
#define NT 391                  // ceil(NN / 128)
#define KP 136                  // padded K stride (bf16 elements)

// ---------------- device-global scratch (no allocations allowed) ----------
__device__ float g_agg[NN * DD];
__device__ float g_inv[NN];
__device__ int   g_cnt[NN];
__device__ float g_Wc[128 * 128];
__device__ float g_Px[NN * 128];   // per-node precomputed x @ Wc[0:64] + be1
__device__ int   g_is64;

__device__ __forceinline__ int load_row(const void* eidx, int i) {
    if (g_is64) return (int)((const long long*)eidx)[i];
    return ((const int*)eidx)[i];
}

// One prologue launch: zero agg (800K float4), zero cnt, detect eidx dtype.
__global__ void prolog_k(const void* eidx, float* agg, int* cnt) {
    int i = blockIdx.x * blockDim.x + threadIdx.x;
    if (i < NN * DD / 4) ((float4*)agg)[i] = make_float4(0.f, 0.f, 0.f, 0.f);
    if (i < NN) cnt[i] = 0;
    if (i == 0) {
        const long long* p = (const long long*)eidx;
        int ok = 1;
        for (int j = 0; j < 64; j++) {
            long long v = p[j];
            if (v < 0 || v >= NN) { ok = 0; break; }
        }
        g_is64 = ok;
    }
}

__global__ void combine_w_k(const float* __restrict__ We1, float* __restrict__ Wc) {
    int i = blockIdx.x * blockDim.x + threadIdx.x;
    if (i < 128 * 128) {
        int k = i >> 7, n = i & 127;
        float v = We1[(k + 64) * 128 + n];
        if (k < 64) v += We1[k * 128 + n];
        Wc[i] = v;
    }
}

__global__ void zero_f4(float* p, int n4) {
    int i = blockIdx.x * blockDim.x + threadIdx.x;
    if (i < n4) ((float4*)p)[i] = make_float4(0.f, 0.f, 0.f, 0.f);
}
__global__ void count_k(const void* eidx, int* cnt) {
    int i = blockIdx.x * blockDim.x + threadIdx.x;
    if (i < EE) atomicAdd(&cnt[load_row(eidx, i)], 1);
}
__global__ void inv_k(const int* __restrict__ cnt, float* __restrict__ inv) {
    int i = blockIdx.x * blockDim.x + threadIdx.x;
    if (i < NN) inv[i] = 1.0f / fmaxf((float)cnt[i], 1.0f);
}

// ---------------- helpers ---------------------------------------------------
__device__ __forceinline__ uint32_t pack_bf2(__nv_bfloat16 a, __nv_bfloat16 b) {
    unsigned short ua = *(unsigned short*)&a, ub = *(unsigned short*)&b;
    return (uint32_t)ua | ((uint32_t)ub << 16);
}

__device__ __forceinline__ void split_pair(float f0, float f1, uint32_t& hi, uint32_t& lo) {
    __nv_bfloat16 h0 = __float2bfloat16_rn(f0);
    __nv_bfloat16 h1 = __float2bfloat16_rn(f1);
    float r0 = f0 - __bfloat162float(h0);
    float r1 = f1 - __bfloat162float(h1);
    hi = pack_bf2(h0, h1);
    lo = pack_bf2(__float2bfloat16_rn(r0), __float2bfloat16_rn(r1));
}

// m16n8k16 row.col bf16 -> f32 accumulate (baseline PTX, sm_80+)
__device__ __forceinline__ void mma_bf16(float* d, const uint32_t* a, const uint32_t* b) {
    asm volatile(
        "mma.sync.aligned.m16n8k16.row.col.f32.bf16.bf16.f32 "
        "{%0,%1,%2,%3}, {%4,%5,%6,%7}, {%8,%9}, {%0,%1,%2,%3};"
        : "+f"(d[0]), "+f"(d[1]), "+f"(d[2]), "+f"(d[3])
        : "r"(a[0]), "r"(a[1]), "r"(a[2]), "r"(a[3]), "r"(b[0]), "r"(b[1]));
}

// ---------------- SMEM layout (bytes) --------------------------------------
#define OFF_AH   0                 // A tile hi  [128][KP] bf16 (also H hi)
#define OFF_AL   34816             // A tile lo
#define OFF_W1H  69632             // W1^T hi    [n=128][KP]
#define OFF_W1L  104448
#define OFF_W2H  139264            // W2^T hi    [n=64][KP]
#define OFF_W2L  156672
#define OFF_B1   174080            // 128 f32
#define OFF_B2   174592            // 64 f32
#define OFF_RW   174848            // 128 int rows
#define SMEMSZ   175360

// ---------------- P precompute: P = x @ Wc[0:64] + be1 ---------------------
__global__ void __launch_bounds__(256, 1)
px_k(const float* __restrict__ x, const float* __restrict__ Wc,
     const float* __restrict__ be1, float* __restrict__ Px)
{
    extern __shared__ char smc[];
    uint16_t* sAh = (uint16_t*)(smc + OFF_AH);
    uint16_t* sAl = (uint16_t*)(smc + OFF_AL);
    uint16_t* sWh = (uint16_t*)(smc + OFF_W1H);
    uint16_t* sWl = (uint16_t*)(smc + OFF_W1L);
    float*    sb1 = (float*)(smc + OFF_B1);

    const int tid = threadIdx.x;
    const int lane = tid & 31, w = tid >> 5;
    const int g = lane >> 2, qt = lane & 3;
    const int wm = w >> 1, wn = w & 1;

    // stage Wc[0:64] transposed+split: sW[n][k], k<64
    {
        int n = tid & 127, k0 = (tid >> 7) * 32;
        for (int k = k0; k < k0 + 32; k += 2) {
            uint32_t hi, lo;
            split_pair(Wc[k * 128 + n], Wc[(k + 1) * 128 + n], hi, lo);
            *(uint32_t*)&sWh[n * KP + k] = hi;
            *(uint32_t*)&sWl[n * KP + k] = lo;
        }
    }
    if (tid < 128) sb1[tid] = be1[tid];
    __syncthreads();

    for (int tile = blockIdx.x; tile < NT; tile += gridDim.x) {
        const int i0 = tile * 128;
        // A build: x rows (K=64), split
        {
            const int m = tid & 127, ch = (tid >> 7) * 32;
            const int gi = i0 + m;
            const bool valid = gi < NN;
            const float* src = x + (size_t)(valid ? gi : 0) * DD + ch;
            #pragma unroll
            for (int c = 0; c < 32; c += 8) {
                float4 f0, f1;
                if (valid) { f0 = *(const float4*)(src + c); f1 = *(const float4*)(src + c + 4); }
                else { f0 = make_float4(0,0,0,0); f1 = f0; }
                uint32_t hw[4], lw[4];
                split_pair(f0.x, f0.y, hw[0], lw[0]);
                split_pair(f0.z, f0.w, hw[1], lw[1]);
                split_pair(f1.x, f1.y, hw[2], lw[2]);
                split_pair(f1.z, f1.w, hw[3], lw[3]);
                int e = m * KP + ch + c;
                *(uint4*)&sAh[e] = *(uint4*)hw;
                *(uint4*)&sAl[e] = *(uint4*)lw;
            }
        }
        __syncthreads();

        float acc[2][8][4];
        #pragma unroll
        for (int mt = 0; mt < 2; mt++)
            #pragma unroll
            for (int nt = 0; nt < 8; nt++)
                #pragma unroll
                for (int j = 0; j < 4; j++) acc[mt][nt][j] = 0.f;

        #pragma unroll
        for (int ks = 0; ks < 4; ks++) {
            const int kb = ks * 16 + 2 * qt;
            uint32_t ah[2][4], al[2][4];
            #pragma unroll
            for (int mt = 0; mt < 2; mt++) {
                int e = (wm * 32 + mt * 16 + g) * KP + kb;
                ah[mt][0] = *(const uint32_t*)&sAh[e];
                ah[mt][1] = *(const uint32_t*)&sAh[e + 8 * KP];
                ah[mt][2] = *(const uint32_t*)&sAh[e + 8];
                ah[mt][3] = *(const uint32_t*)&sAh[e + 8 * KP + 8];
                al[mt][0] = *(const uint32_t*)&sAl[e];
                al[mt][1] = *(const uint32_t*)&sAl[e + 8 * KP];
                al[mt][2] = *(const uint32_t*)&sAl[e + 8];
                al[mt][3] = *(const uint32_t*)&sAl[e + 8 * KP + 8];
            }
            #pragma unroll
            for (int nt = 0; nt < 8; nt++) {
                int e = (wn * 64 + nt * 8 + g) * KP + kb;
                uint32_t bh[2], bl[2];
                bh[0] = *(const uint32_t*)&sWh[e];
                bh[1] = *(const uint32_t*)&sWh[e + 8];
                bl[0] = *(const uint32_t*)&sWl[e];
                bl[1] = *(const uint32_t*)&sWl[e + 8];
                mma_bf16(acc[0][nt], ah[0], bh);
                mma_bf16(acc[1][nt], ah[1], bh);
                mma_bf16(acc[0][nt], ah[0], bl);
                mma_bf16(acc[1][nt], ah[1], bl);
                mma_bf16(acc[0][nt], al[0], bh);
                mma_bf16(acc[1][nt], al[1], bh);
            }
        }

        // store P = acc + be1
        #pragma unroll
        for (int mt = 0; mt < 2; mt++)
            #pragma unroll
            for (int nt = 0; nt < 8; nt++) {
                int rl = wm * 32 + mt * 16 + g;
                int col = wn * 64 + nt * 8 + 2 * qt;
                #pragma unroll
                for (int rh = 0; rh < 2; rh++) {
                    int gi = i0 + rl + rh * 8;
                    if (gi >= NN) continue;
                    float2 v = make_float2(acc[mt][nt][rh * 2] + sb1[col],
                                           acc[mt][nt][rh * 2 + 1] + sb1[col + 1]);
                    *(float2*)&Px[(size_t)gi * 128 + col] = v;
                }
            }
        __syncthreads();
    }
}

// Fused 2-layer MLP on HMMA with bf16 split-2, persistent CTAs.
// EDGE: D1 = Px[row] (acc init, bias folded) + ea @ Wc[64:128] (K=64);
//       H = relu(D1); D2 = H @ We2; red.add agg[row] += D2+b2; dst = ea + D2+b2
// !EDGE: A = [x | agg*inv]; D1 = A @ Wn1 + bn1; H = relu; D2 = H @ Wn2;
//        dst = x + D2+b2
template <bool EDGE>
__global__ void __launch_bounds__(256, 1)
gnn_mma(const float* __restrict__ x_src, const float* __restrict__ a_src,
        const void* __restrict__ eidx, const float* __restrict__ Px,
        const float* __restrict__ W1, const float* __restrict__ b1,
        const float* __restrict__ W2, const float* __restrict__ b2,
        float* __restrict__ dst, float* __restrict__ agg,
        const float* __restrict__ inv, int ntiles, int count)
{
    extern __shared__ char smc[];
    uint16_t* sAh  = (uint16_t*)(smc + OFF_AH);
    uint16_t* sAl  = (uint16_t*)(smc + OFF_AL);
    uint16_t* sW1h = (uint16_t*)(smc + OFF_W1H);
    uint16_t* sW1l = (uint16_t*)(smc + OFF_W1L);
    uint16_t* sW2h = (uint16_t*)(smc + OFF_W2H);
    uint16_t* sW2l = (uint16_t*)(smc + OFF_W2L);
    float*    sb1  = (float*)(smc + OFF_B1);
    float*    sb2  = (float*)(smc + OFF_B2);
    int*      sRows = (int*)(smc + OFF_RW);

    const int tid = threadIdx.x;
    const int lane = tid & 31, w = tid >> 5;
    const int g = lane >> 2, qt = lane & 3;
    const int wm = w >> 1, wn = w & 1;

    // ---- stage split-transposed weights once (persistent CTA) ----
    if (EDGE) {
        // Wc rows 64..127 -> sW1[n][k], k<64
        int n = tid & 127, k0 = (tid >> 7) * 32;
        for (int k = k0; k < k0 + 32; k += 2) {
            uint32_t hi, lo;
            split_pair(W1[(64 + k) * 128 + n], W1[(65 + k) * 128 + n], hi, lo);
            *(uint32_t*)&sW1h[n * KP + k] = hi;
            *(uint32_t*)&sW1l[n * KP + k] = lo;
        }
    } else {
        int n = tid & 127, k0 = (tid >> 7) * 64;
        for (int k = k0; k < k0 + 64; k += 2) {
            uint32_t hi, lo;
            split_pair(W1[k * 128 + n], W1[(k + 1) * 128 + n], hi, lo);
            *(uint32_t*)&sW1h[n * KP + k] = hi;
            *(uint32_t*)&sW1l[n * KP + k] = lo;
        }
    }
    {
        int n = tid & 63, k0 = (tid >> 6) * 32;
        for (int k = k0; k < k0 + 32; k += 2) {
            uint32_t hi, lo;
            split_pair(W2[k * 64 + n], W2[(k + 1) * 64 + n], hi, lo);
            *(uint32_t*)&sW2h[n * KP + k] = hi;
            *(uint32_t*)&sW2l[n * KP + k] = lo;
        }
    }
    if (tid < 128) sb1[tid] = EDGE ? 0.f : b1[tid];
    if (tid < 64)  sb2[tid] = b2[tid];
    __syncthreads();

    for (int tile = blockIdx.x; tile < ntiles; tile += gridDim.x) {
        const int i0 = tile * 128;

        if (EDGE) {
            if (tid < 128) sRows[tid] = load_row(eidx, i0 + tid);
            __syncthreads();
        }

        // ---- build A tile (bf16 split, row-major [m][KP]) ----
        if (EDGE) {
            // only edge_attr, K=64
            const int m = tid & 127, ch = (tid >> 7) * 32;
            const float* src = a_src + (size_t)(i0 + m) * DD + ch;
            #pragma unroll
            for (int c = 0; c < 32; c += 8) {
                float4 f0 = *(const float4*)(src + c);
                float4 f1 = *(const float4*)(src + c + 4);
                uint32_t hw[4], lw[4];
                split_pair(f0.x, f0.y, hw[0], lw[0]);
                split_pair(f0.z, f0.w, hw[1], lw[1]);
                split_pair(f1.x, f1.y, hw[2], lw[2]);
                split_pair(f1.z, f1.w, hw[3], lw[3]);
                int e = m * KP + ch + c;
                *(uint4*)&sAh[e] = *(uint4*)hw;
                *(uint4*)&sAl[e] = *(uint4*)lw;
            }
        } else {
            const int m = tid & 127, half = tid >> 7;
            const int gi = i0 + m;
            const bool valid = gi < count;
            const float* src;
            float scale = 1.0f;
            bool doscale = false;
            if (half == 0) {
                src = x_src + (size_t)(valid ? gi : 0) * DD;
            } else {
                src = a_src + (size_t)(valid ? gi : 0) * DD;
                scale = valid ? inv[gi] : 0.0f;
                doscale = true;
            }
            #pragma unroll
            for (int c = 0; c < 64; c += 8) {
                float4 f0 = *(const float4*)(src + c);
                float4 f1 = *(const float4*)(src + c + 4);
                if (doscale) {
                    f0.x *= scale; f0.y *= scale; f0.z *= scale; f0.w *= scale;
                    f1.x *= scale; f1.y *= scale; f1.z *= scale; f1.w *= scale;
                }
                uint32_t hw[4], lw[4];
                split_pair(f0.x, f0.y, hw[0], lw[0]);
                split_pair(f0.z, f0.w, hw[1], lw[1]);
                split_pair(f1.x, f1.y, hw[2], lw[2]);
                split_pair(f1.z, f1.w, hw[3], lw[3]);
                int e = m * KP + half * 64 + c;
                *(uint4*)&sAh[e] = *(uint4*)hw;
                *(uint4*)&sAl[e] = *(uint4*)lw;
            }
        }

        // ---- init acc: EDGE gathers Px[row] (bias folded); node zeros ----
        float acc[2][8][4];
        if (EDGE) {
            #pragma unroll
            for (int mt = 0; mt < 2; mt++)
                #pragma unroll
                for (int nt = 0; nt < 8; nt++) {
                    int rl = wm * 32 + mt * 16 + g;
                    int col = wn * 64 + nt * 8 + 2 * qt;
                    float2 v0 = *(const float2*)&Px[(size_t)sRows[rl] * 128 + col];
                    float2 v1 = *(const float2*)&Px[(size_t)sRows[rl + 8] * 128 + col];
                    acc[mt][nt][0] = v0.x; acc[mt][nt][1] = v0.y;
                    acc[mt][nt][2] = v1.x; acc[mt][nt][3] = v1.y;
                }
        } else {
            #pragma unroll
            for (int mt = 0; mt < 2; mt++)
                #pragma unroll
                for (int nt = 0; nt < 8; nt++)
                    #pragma unroll
                    for (int j = 0; j < 4; j++) acc[mt][nt][j] = 0.f;
        }
        __syncthreads();

        // ---- GEMM1: K=64 (EDGE) / K=128 (node), 3 split terms ----
        constexpr int KS1 = EDGE ? 4 : 8;
        #pragma unroll
        for (int ks = 0; ks < KS1; ks++) {
            const int kb = ks * 16 + 2 * qt;
            uint32_t ah[2][4], al[2][4];
            #pragma unroll
            for (int mt = 0; mt < 2; mt++) {
                int e = (wm * 32 + mt * 16 + g) * KP + kb;
                ah[mt][0] = *(const uint32_t*)&sAh[e];
                ah[mt][1] = *(const uint32_t*)&sAh[e + 8 * KP];
                ah[mt][2] = *(const uint32_t*)&sAh[e + 8];
                ah[mt][3] = *(const uint32_t*)&sAh[e + 8 * KP + 8];
                al[mt][0] = *(const uint32_t*)&sAl[e];
                al[mt][1] = *(const uint32_t*)&sAl[e + 8 * KP];
                al[mt][2] = *(const uint32_t*)&sAl[e + 8];
                al[mt][3] = *(const uint32_t*)&sAl[e + 8 * KP + 8];
            }
            #pragma unroll
            for (int nt = 0; nt < 8; nt++) {
                int e = (wn * 64 + nt * 8 + g) * KP + kb;
                uint32_t bh[2], bl[2];
                bh[0] = *(const uint32_t*)&sW1h[e];
                bh[1] = *(const uint32_t*)&sW1h[e + 8];
                bl[0] = *(const uint32_t*)&sW1l[e];
                bl[1] = *(const uint32_t*)&sW1l[e + 8];
                mma_bf16(acc[0][nt], ah[0], bh);
                mma_bf16(acc[1][nt], ah[1], bh);
                mma_bf16(acc[0][nt], ah[0], bl);
                mma_bf16(acc[1][nt], ah[1], bl);
                mma_bf16(acc[0][nt], al[0], bh);
                mma_bf16(acc[1][nt], al[1], bh);
            }
        }
        __syncthreads();   // all A reads done -> safe to overwrite with H

        // ---- H = relu(D1 [+ b1]) -> split back into A buffers ----
        #pragma unroll
        for (int mt = 0; mt < 2; mt++)
            #pragma unroll
            for (int nt = 0; nt < 8; nt++) {
                int row = wm * 32 + mt * 16 + g;
                int col = wn * 64 + nt * 8 + 2 * qt;
                float v0 = fmaxf(acc[mt][nt][0] + sb1[col], 0.f);
                float v1 = fmaxf(acc[mt][nt][1] + sb1[col + 1], 0.f);
                float v2 = fmaxf(acc[mt][nt][2] + sb1[col], 0.f);
                float v3 = fmaxf(acc[mt][nt][3] + sb1[col + 1], 0.f);
                uint32_t hi, lo;
                split_pair(v0, v1, hi, lo);
                *(uint32_t*)&sAh[row * KP + col] = hi;
                *(uint32_t*)&sAl[row * KP + col] = lo;
                split_pair(v2, v3, hi, lo);
                *(uint32_t*)&sAh[(row + 8) * KP + col] = hi;
                *(uint32_t*)&sAl[(row + 8) * KP + col] = lo;
            }
        __syncthreads();

        // ---- GEMM2: D2 = H @ W2 (K=128), 3 split terms ----
        float acc2[2][4][4];
        #pragma unroll
        for (int mt = 0; mt < 2; mt++)
            #pragma unroll
            for (int nt = 0; nt < 4; nt++)
                #pragma unroll
                for (int j = 0; j < 4; j++) acc2[mt][nt][j] = 0.f;

        #pragma unroll
        for (int ks = 0; ks < 8; ks++) {
            const int kb = ks * 16 + 2 * qt;
            uint32_t ah[2][4], al[2][4];
            #pragma unroll
            for (int mt = 0; mt < 2; mt++) {
                int e = (wm * 32 + mt * 16 + g) * KP + kb;
                ah[mt][0] = *(const uint32_t*)&sAh[e];
                ah[mt][1] = *(const uint32_t*)&sAh[e + 8 * KP];
                ah[mt][2] = *(const uint32_t*)&sAh[e + 8];
                ah[mt][3] = *(const uint32_t*)&sAh[e + 8 * KP + 8];
                al[mt][0] = *(const uint32_t*)&sAl[e];
                al[mt][1] = *(const uint32_t*)&sAl[e + 8 * KP];
                al[mt][2] = *(const uint32_t*)&sAl[e + 8];
                al[mt][3] = *(const uint32_t*)&sAl[e + 8 * KP + 8];
            }
            #pragma unroll
            for (int nt = 0; nt < 4; nt++) {
                int e = (wn * 32 + nt * 8 + g) * KP + kb;
                uint32_t bh[2], bl[2];
                bh[0] = *(const uint32_t*)&sW2h[e];
                bh[1] = *(const uint32_t*)&sW2h[e + 8];
                bl[0] = *(const uint32_t*)&sW2l[e];
                bl[1] = *(const uint32_t*)&sW2l[e + 8];
                mma_bf16(acc2[0][nt], ah[0], bh);
                mma_bf16(acc2[1][nt], ah[1], bh);
                mma_bf16(acc2[0][nt], ah[0], bl);
                mma_bf16(acc2[1][nt], ah[1], bl);
                mma_bf16(acc2[0][nt], al[0], bh);
                mma_bf16(acc2[1][nt], al[1], bh);
            }
        }

        // ---- epilogue: out = residual + (D2 + b2); EDGE also scatter-add ----
        {
            const float* res = EDGE ? a_src : x_src;
            #pragma unroll
            for (int mt = 0; mt < 2; mt++)
                #pragma unroll
                for (int nt = 0; nt < 4; nt++) {
                    int rl = wm * 32 + mt * 16 + g;
                    int col = wn * 32 + nt * 8 + 2 * qt;
                    #pragma unroll
                    for (int rh = 0; rh < 2; rh++) {
                        int row = rl + rh * 8;
                        int gi = i0 + row;
                        if (!EDGE && gi >= count) continue;
                        float vx = acc2[mt][nt][rh * 2 + 0] + sb2[col];
                        float vy = acc2[mt][nt][rh * 2 + 1] + sb2[col + 1];
                        if (EDGE) {
                            float* ap = agg + (size_t)sRows[row] * DD + col;
                            asm volatile("red.global.add.v2.f32 [%0], {%1, %2};"
                                         :: "l"(ap), "f"(vx), "f"(vy) : "memory");
                        }
                        float2 rv = *(const float2*)(res + (size_t)gi * DD + col);
                        float2 ov = make_float2(rv.x + vx, rv.y + vy);
                        *(float2*)(dst + (size_t)gi * DD + col) = ov;
                    }
                }
        }
        __syncthreads();
    }
}

extern "C" void kernel_launch(void* const* d_in, const int* in_sizes, int n_in,
                              void* d_out, int out_size)
{
    const float* x   = (const float*)d_in[0];
    const float* ea  = (const float*)d_in[1];
    const float* We1 = (const float*)d_in[2];
    const float* be1 = (const float*)d_in[3];
    const float* We2 = (const float*)d_in[4];
    const float* be2 = (const float*)d_in[5];
    const float* Wn1 = (const float*)d_in[6];
    const float* bn1 = (const float*)d_in[7];
    const float* Wn2 = (const float*)d_in[8];
    const float* bn2 = (const float*)d_in[9];
    const void*  eidx = d_in[10];

    float* out_x  = (float*)d_out;
    float* out_ea = (float*)d_out + (size_t)NN * DD;

    float *agg, *inv, *Wc, *Px;
    int* cnt;
    cudaGetSymbolAddress((void**)&agg, g_agg);
    cudaGetSymbolAddress((void**)&inv, g_inv);
    cudaGetSymbolAddress((void**)&cnt, g_cnt);
    cudaGetSymbolAddress((void**)&Wc,  g_Wc);
    cudaGetSymbolAddress((void**)&Px,  g_Px);

    cudaFuncSetAttribute(gnn_mma<true>,  cudaFuncAttributeMaxDynamicSharedMemorySize, SMEMSZ);
    cudaFuncSetAttribute(gnn_mma<false>, cudaFuncAttributeMaxDynamicSharedMemorySize, SMEMSZ);
    cudaFuncSetAttribute(px_k,           cudaFuncAttributeMaxDynamicSharedMemorySize, SMEMSZ);

    int smcount = 148;
    cudaDeviceGetAttribute(&smcount, cudaDevAttrMultiProcessorCount, 0);
    int ge = smcount < ET ? smcount : ET;
    int gn = smcount < NT ? smcount : NT;

    // Launch order: edge gnn_mma is my 4th launch (global #6 incl. 2 harness
    // launches; ncu -s 5 captures it).
    prolog_k<<<(NN * DD / 4 + 255) / 256, 256>>>(eidx, agg, cnt);        // 0
    combine_w_k<<<(128 * 128 + 255) / 256, 256>>>(We1, Wc);              // 1
    px_k<<<gn, 256, SMEMSZ>>>(x, Wc, be1, Px);                           // 2
    gnn_mma<true><<<ge, 256, SMEMSZ>>>(                                  // 3 <- profiled
        x, ea, eidx, Px, Wc, be1, We2, be2, out_ea, agg, nullptr, ET, EE);
    count_k<<<(EE + 255) / 256, 256>>>(eidx, cnt);                       // 4
    inv_k<<<(NN + 255) / 256, 256>>>(cnt, inv);                          // 5
    gnn_mma<false><<<gn, 256, SMEMSZ>>>(                                 // 6
        x, agg, nullptr, nullptr, Wn1, bn1, Wn2, bn2, out_x, nullptr, inv, NT, NN);

    // iteration 2
    zero_f4<<<(NN * DD / 4 + 255) / 256, 256>>>(agg, NN * DD / 4);
    px_k<<<gn, 256, SMEMSZ>>>(out_x, Wc, be1, Px);
    gnn_mma<true><<<ge, 256, SMEMSZ>>>(
        out_x, out_ea, eidx, Px, Wc, be1, We2, be2, out_ea, agg, nullptr, ET, EE);
    gnn_mma<false><<<gn, 256, SMEMSZ>>>(
        out_x, agg, nullptr, nullptr, Wn1, bn1, Wn2, bn2, out_x, nullptr, inv, NT, NN);
}

// round 7
// speedup vs baseline: 2.6296x; 1.2066x over previous
#include <cuda_runtime.h>
#include <cuda_bf16.h>
#include <cstdint>

#define NN 50000
#define EE 800000
#define DD 64
#define ET 6250                 // EE / 128
#define NT 391                  // ceil(NN / 128)
#define KP 136                  // node-kernel padded K stride (bf16)

// ---------------- device-global scratch (no allocations allowed) ----------
__device__ float g_agg[NN * DD];
__device__ float g_inv[NN];
__device__ int   g_cnt[NN];
__device__ float g_Wc[128 * 128];
__device__ float g_Px[NN * 128];   // per-node x @ Wc[0:64] + be1
__device__ int   g_is64;

__device__ __forceinline__ int load_row(const void* eidx, int i) {
    if (g_is64) return (int)((const long long*)eidx)[i];
    return ((const int*)eidx)[i];
}

// One prologue launch: zero agg, zero cnt, detect eidx dtype.
__global__ void prolog_k(const void* eidx, float* agg, int* cnt) {
    int i = blockIdx.x * blockDim.x + threadIdx.x;
    if (i < NN * DD / 4) ((float4*)agg)[i] = make_float4(0.f, 0.f, 0.f, 0.f);
    if (i < NN) cnt[i] = 0;
    if (i == 0) {
        const long long* p = (const long long*)eidx;
        int ok = 1;
        for (int j = 0; j < 64; j++) {
            long long v = p[j];
            if (v < 0 || v >= NN) { ok = 0; break; }
        }
        g_is64 = ok;
    }
}

__global__ void combine_w_k(const float* __restrict__ We1, float* __restrict__ Wc) {
    int i = blockIdx.x * blockDim.x + threadIdx.x;
    if (i < 128 * 128) {
        int k = i >> 7, n = i & 127;
        float v = We1[(k + 64) * 128 + n];
        if (k < 64) v += We1[k * 128 + n];
        Wc[i] = v;
    }
}

__global__ void zero_f4(float* p, int n4) {
    int i = blockIdx.x * blockDim.x + threadIdx.x;
    if (i < n4) ((float4*)p)[i] = make_float4(0.f, 0.f, 0.f, 0.f);
}
__global__ void count_k(const void* eidx, int* cnt) {
    int i = blockIdx.x * blockDim.x + threadIdx.x;
    if (i < EE) atomicAdd(&cnt[load_row(eidx, i)], 1);
}
__global__ void inv_k(const int* __restrict__ cnt, float* __restrict__ inv) {
    int i = blockIdx.x * blockDim.x + threadIdx.x;
    if (i < NN) inv[i] = 1.0f / fmaxf((float)cnt[i], 1.0f);
}

// ---------------- helpers ---------------------------------------------------
__device__ __forceinline__ uint32_t pack_bf2(__nv_bfloat16 a, __nv_bfloat16 b) {
    unsigned short ua = *(unsigned short*)&a, ub = *(unsigned short*)&b;
    return (uint32_t)ua | ((uint32_t)ub << 16);
}

__device__ __forceinline__ void split_pair(float f0, float f1, uint32_t& hi, uint32_t& lo) {
    __nv_bfloat16 h0 = __float2bfloat16_rn(f0);
    __nv_bfloat16 h1 = __float2bfloat16_rn(f1);
    float r0 = f0 - __bfloat162float(h0);
    float r1 = f1 - __bfloat162float(h1);
    hi = pack_bf2(h0, h1);
    lo = pack_bf2(__float2bfloat16_rn(r0), __float2bfloat16_rn(r1));
}

// m16n8k16 row.col bf16 -> f32 accumulate (baseline PTX, sm_80+)
__device__ __forceinline__ void mma_bf16(float* d, const uint32_t* a, const uint32_t* b) {
    asm volatile(
        "mma.sync.aligned.m16n8k16.row.col.f32.bf16.bf16.f32 "
        "{%0,%1,%2,%3}, {%4,%5,%6,%7}, {%8,%9}, {%0,%1,%2,%3};"
        : "+f"(d[0]), "+f"(d[1]), "+f"(d[2]), "+f"(d[3])
        : "r"(a[0]), "r"(a[1]), "r"(a[2]), "r"(a[3]), "r"(b[0]), "r"(b[1]));
}

// ================= EDGE KERNEL (2 CTAs/SM, H in registers) =================
// warp tile: 16 rows x full N. GEMM1: D1 = Px[row] + ea @ Wc[64:128] (K=64).
// relu in-place; H packed to bf16-split on the fly inside GEMM2 k-loop.
#define E_KP  72                  // K=64 + 8 pad (bf16 elems)
#define E_KP2 136                 // W2 stride, K=128 + 8
#define E_AH  0                   // [128][72] bf16
#define E_AL  18432
#define E_W1H 36864               // [128n][72]
#define E_W1L 55296
#define E_W2H 73728               // [64n][136]
#define E_W2L 91136
#define E_B2  108544              // 64 f32
#define E_SMEM 108800

__global__ void __launch_bounds__(256, 2)
edge_mma(const float* __restrict__ ea, const void* __restrict__ eidx,
         const float* __restrict__ Px,
         const float* __restrict__ Wc, const float* __restrict__ W2,
         const float* __restrict__ b2,
         float* __restrict__ dst, float* __restrict__ agg, int ntiles)
{
    extern __shared__ char smc[];
    uint16_t* sAh  = (uint16_t*)(smc + E_AH);
    uint16_t* sAl  = (uint16_t*)(smc + E_AL);
    uint16_t* sW1h = (uint16_t*)(smc + E_W1H);
    uint16_t* sW1l = (uint16_t*)(smc + E_W1L);
    uint16_t* sW2h = (uint16_t*)(smc + E_W2H);
    uint16_t* sW2l = (uint16_t*)(smc + E_W2L);
    float*    sb2  = (float*)(smc + E_B2);

    const int tid = threadIdx.x;
    const int lane = tid & 31, w = tid >> 5;
    const int g = lane >> 2, qt = lane & 3;

    // ---- stage weights once: W1 = Wc rows 64:127 (K=64), W2 (K=128) ----
    {
        int n = tid & 127, k0 = (tid >> 7) * 32;
        for (int k = k0; k < k0 + 32; k += 2) {
            uint32_t hi, lo;
            split_pair(Wc[(64 + k) * 128 + n], Wc[(65 + k) * 128 + n], hi, lo);
            *(uint32_t*)&sW1h[n * E_KP + k] = hi;
            *(uint32_t*)&sW1l[n * E_KP + k] = lo;
        }
    }
    {
        int n = tid & 63, k0 = (tid >> 6) * 32;
        for (int k = k0; k < k0 + 32; k += 2) {
            uint32_t hi, lo;
            split_pair(W2[k * 64 + n], W2[(k + 1) * 64 + n], hi, lo);
            *(uint32_t*)&sW2h[n * E_KP2 + k] = hi;
            *(uint32_t*)&sW2l[n * E_KP2 + k] = lo;
        }
    }
    if (tid < 64) sb2[tid] = b2[tid];
    __syncthreads();

    for (int tile = blockIdx.x; tile < ntiles; tile += gridDim.x) {
        const int i0 = tile * 128;
        const int mrow0 = 16 * w + g;          // warp-local rows g, g+8

        // per-thread target rows (redundant across qt, coalesced)
        const int r0 = load_row(eidx, i0 + mrow0);
        const int r1 = load_row(eidx, i0 + mrow0 + 8);

        // ---- init acc1 from Px gather (bias be1 folded into Px) ----
        float acc1[16][4];
        #pragma unroll
        for (int nt = 0; nt < 16; nt++) {
            int col = 8 * nt + 2 * qt;
            float2 v0 = *(const float2*)&Px[(size_t)r0 * 128 + col];
            float2 v1 = *(const float2*)&Px[(size_t)r1 * 128 + col];
            acc1[nt][0] = v0.x; acc1[nt][1] = v0.y;
            acc1[nt][2] = v1.x; acc1[nt][3] = v1.y;
        }

        // ---- build A tile from ea (K=64), bf16 split ----
        {
            const int m = tid & 127, kh = (tid >> 7) * 32;
            const float* src = ea + (size_t)(i0 + m) * DD + kh;
            #pragma unroll
            for (int c = 0; c < 32; c += 8) {
                float4 f0 = *(const float4*)(src + c);
                float4 f1 = *(const float4*)(src + c + 4);
                uint32_t hw[4], lw[4];
                split_pair(f0.x, f0.y, hw[0], lw[0]);
                split_pair(f0.z, f0.w, hw[1], lw[1]);
                split_pair(f1.x, f1.y, hw[2], lw[2]);
                split_pair(f1.z, f1.w, hw[3], lw[3]);
                int e = m * E_KP + kh + c;
                *(uint4*)&sAh[e] = *(uint4*)hw;
                *(uint4*)&sAl[e] = *(uint4*)lw;
            }
        }
        __syncthreads();

        // ---- GEMM1: acc1 += ea @ W1 (K=64, 3 split terms) ----
        #pragma unroll
        for (int ks = 0; ks < 4; ks++) {
            const int kb = ks * 16 + 2 * qt;
            uint32_t ah[4], al[4];
            {
                int e = mrow0 * E_KP + kb;
                ah[0] = *(const uint32_t*)&sAh[e];
                ah[1] = *(const uint32_t*)&sAh[e + 8 * E_KP];
                ah[2] = *(const uint32_t*)&sAh[e + 8];
                ah[3] = *(const uint32_t*)&sAh[e + 8 * E_KP + 8];
                al[0] = *(const uint32_t*)&sAl[e];
                al[1] = *(const uint32_t*)&sAl[e + 8 * E_KP];
                al[2] = *(const uint32_t*)&sAl[e + 8];
                al[3] = *(const uint32_t*)&sAl[e + 8 * E_KP + 8];
            }
            #pragma unroll
            for (int nt = 0; nt < 16; nt++) {
                int e = (8 * nt + g) * E_KP + kb;
                uint32_t bh[2], bl[2];
                bh[0] = *(const uint32_t*)&sW1h[e];
                bh[1] = *(const uint32_t*)&sW1h[e + 8];
                bl[0] = *(const uint32_t*)&sW1l[e];
                bl[1] = *(const uint32_t*)&sW1l[e + 8];
                mma_bf16(acc1[nt], ah, bh);
                mma_bf16(acc1[nt], ah, bl);
                mma_bf16(acc1[nt], al, bh);
            }
        }
        __syncthreads();   // all sA reads done -> next tile may rebuild A

        // ---- relu in place (be1 already folded via Px) ----
        #pragma unroll
        for (int nt = 0; nt < 16; nt++)
            #pragma unroll
            for (int j = 0; j < 4; j++)
                acc1[nt][j] = fmaxf(acc1[nt][j], 0.f);

        // ---- GEMM2: acc2 = H @ W2 (K=128); H packed from acc1 per k-step ----
        float acc2[8][4];
        #pragma unroll
        for (int nt = 0; nt < 8; nt++)
            #pragma unroll
            for (int j = 0; j < 4; j++) acc2[nt][j] = 0.f;

        #pragma unroll
        for (int ks = 0; ks < 8; ks++) {
            // acc1[2ks], acc1[2ks+1] ARE this k-step's A fragment (rows g,g+8)
            uint32_t ah[4], al[4];
            split_pair(acc1[2 * ks][0],     acc1[2 * ks][1],     ah[0], al[0]);
            split_pair(acc1[2 * ks][2],     acc1[2 * ks][3],     ah[1], al[1]);
            split_pair(acc1[2 * ks + 1][0], acc1[2 * ks + 1][1], ah[2], al[2]);
            split_pair(acc1[2 * ks + 1][2], acc1[2 * ks + 1][3], ah[3], al[3]);
            const int kb = ks * 16 + 2 * qt;
            #pragma unroll
            for (int nt = 0; nt < 8; nt++) {
                int e = (8 * nt + g) * E_KP2 + kb;
                uint32_t bh[2], bl[2];
                bh[0] = *(const uint32_t*)&sW2h[e];
                bh[1] = *(const uint32_t*)&sW2h[e + 8];
                bl[0] = *(const uint32_t*)&sW2l[e];
                bl[1] = *(const uint32_t*)&sW2l[e + 8];
                mma_bf16(acc2[nt], ah, bh);
                mma_bf16(acc2[nt], ah, bl);
                mma_bf16(acc2[nt], al, bh);
            }
        }

        // ---- epilogue: red.add agg[row]; dst = ea + (D2 + b2) ----
        #pragma unroll
        for (int nt = 0; nt < 8; nt++) {
            int col = 8 * nt + 2 * qt;
            float vx0 = acc2[nt][0] + sb2[col];
            float vy0 = acc2[nt][1] + sb2[col + 1];
            float vx1 = acc2[nt][2] + sb2[col];
            float vy1 = acc2[nt][3] + sb2[col + 1];
            float* ap0 = agg + (size_t)r0 * DD + col;
            float* ap1 = agg + (size_t)r1 * DD + col;
            asm volatile("red.global.add.v2.f32 [%0], {%1, %2};"
                         :: "l"(ap0), "f"(vx0), "f"(vy0) : "memory");
            asm volatile("red.global.add.v2.f32 [%0], {%1, %2};"
                         :: "l"(ap1), "f"(vx1), "f"(vy1) : "memory");
            size_t o0 = (size_t)(i0 + mrow0) * DD + col;
            size_t o1 = (size_t)(i0 + mrow0 + 8) * DD + col;
            float2 e0 = *(const float2*)(ea + o0);
            float2 e1 = *(const float2*)(ea + o1);
            *(float2*)(dst + o0) = make_float2(e0.x + vx0, e0.y + vy0);
            *(float2*)(dst + o1) = make_float2(e1.x + vx1, e1.y + vy1);
        }
    }
}

// ---------------- node / px kernels (round-6 layout, unchanged) ------------
#define OFF_AH   0
#define OFF_AL   34816
#define OFF_W1H  69632
#define OFF_W1L  104448
#define OFF_W2H  139264
#define OFF_W2L  156672
#define OFF_B1   174080
#define OFF_B2   174592
#define SMEMSZ   175360

__global__ void __launch_bounds__(256, 1)
px_k(const float* __restrict__ x, const float* __restrict__ Wc,
     const float* __restrict__ be1, float* __restrict__ Px)
{
    extern __shared__ char smc[];
    uint16_t* sAh = (uint16_t*)(smc + OFF_AH);
    uint16_t* sAl = (uint16_t*)(smc + OFF_AL);
    uint16_t* sWh = (uint16_t*)(smc + OFF_W1H);
    uint16_t* sWl = (uint16_t*)(smc + OFF_W1L);
    float*    sb1 = (float*)(smc + OFF_B1);

    const int tid = threadIdx.x;
    const int lane = tid & 31, w = tid >> 5;
    const int g = lane >> 2, qt = lane & 3;
    const int wm = w >> 1, wn = w & 1;

    {
        int n = tid & 127, k0 = (tid >> 7) * 32;
        for (int k = k0; k < k0 + 32; k += 2) {
            uint32_t hi, lo;
            split_pair(Wc[k * 128 + n], Wc[(k + 1) * 128 + n], hi, lo);
            *(uint32_t*)&sWh[n * KP + k] = hi;
            *(uint32_t*)&sWl[n * KP + k] = lo;
        }
    }
    if (tid < 128) sb1[tid] = be1[tid];
    __syncthreads();

    for (int tile = blockIdx.x; tile < NT; tile += gridDim.x) {
        const int i0 = tile * 128;
        {
            const int m = tid & 127, ch = (tid >> 7) * 32;
            const int gi = i0 + m;
            const bool valid = gi < NN;
            const float* src = x + (size_t)(valid ? gi : 0) * DD + ch;
            #pragma unroll
            for (int c = 0; c < 32; c += 8) {
                float4 f0, f1;
                if (valid) { f0 = *(const float4*)(src + c); f1 = *(const float4*)(src + c + 4); }
                else { f0 = make_float4(0,0,0,0); f1 = f0; }
                uint32_t hw[4], lw[4];
                split_pair(f0.x, f0.y, hw[0], lw[0]);
                split_pair(f0.z, f0.w, hw[1], lw[1]);
                split_pair(f1.x, f1.y, hw[2], lw[2]);
                split_pair(f1.z, f1.w, hw[3], lw[3]);
                int e = m * KP + ch + c;
                *(uint4*)&sAh[e] = *(uint4*)hw;
                *(uint4*)&sAl[e] = *(uint4*)lw;
            }
        }
        __syncthreads();

        float acc[2][8][4];
        #pragma unroll
        for (int mt = 0; mt < 2; mt++)
            #pragma unroll
            for (int nt = 0; nt < 8; nt++)
                #pragma unroll
                for (int j = 0; j < 4; j++) acc[mt][nt][j] = 0.f;

        #pragma unroll
        for (int ks = 0; ks < 4; ks++) {
            const int kb = ks * 16 + 2 * qt;
            uint32_t ah[2][4], al[2][4];
            #pragma unroll
            for (int mt = 0; mt < 2; mt++) {
                int e = (wm * 32 + mt * 16 + g) * KP + kb;
                ah[mt][0] = *(const uint32_t*)&sAh[e];
                ah[mt][1] = *(const uint32_t*)&sAh[e + 8 * KP];
                ah[mt][2] = *(const uint32_t*)&sAh[e + 8];
                ah[mt][3] = *(const uint32_t*)&sAh[e + 8 * KP + 8];
                al[mt][0] = *(const uint32_t*)&sAl[e];
                al[mt][1] = *(const uint32_t*)&sAl[e + 8 * KP];
                al[mt][2] = *(const uint32_t*)&sAl[e + 8];
                al[mt][3] = *(const uint32_t*)&sAl[e + 8 * KP + 8];
            }
            #pragma unroll
            for (int nt = 0; nt < 8; nt++) {
                int e = (wn * 64 + nt * 8 + g) * KP + kb;
                uint32_t bh[2], bl[2];
                bh[0] = *(const uint32_t*)&sWh[e];
                bh[1] = *(const uint32_t*)&sWh[e + 8];
                bl[0] = *(const uint32_t*)&sWl[e];
                bl[1] = *(const uint32_t*)&sWl[e + 8];
                mma_bf16(acc[0][nt], ah[0], bh);
                mma_bf16(acc[1][nt], ah[1], bh);
                mma_bf16(acc[0][nt], ah[0], bl);
                mma_bf16(acc[1][nt], ah[1], bl);
                mma_bf16(acc[0][nt], al[0], bh);
                mma_bf16(acc[1][nt], al[1], bh);
            }
        }

        #pragma unroll
        for (int mt = 0; mt < 2; mt++)
            #pragma unroll
            for (int nt = 0; nt < 8; nt++) {
                int rl = wm * 32 + mt * 16 + g;
                int col = wn * 64 + nt * 8 + 2 * qt;
                #pragma unroll
                for (int rh = 0; rh < 2; rh++) {
                    int gi = i0 + rl + rh * 8;
                    if (gi >= NN) continue;
                    float2 v = make_float2(acc[mt][nt][rh * 2] + sb1[col],
                                           acc[mt][nt][rh * 2 + 1] + sb1[col + 1]);
                    *(float2*)&Px[(size_t)gi * 128 + col] = v;
                }
            }
        __syncthreads();
    }
}

// node MLP (round-6 version, EDGE=false path only)
__global__ void __launch_bounds__(256, 1)
node_mma(const float* __restrict__ x_src, const float* __restrict__ a_src,
         const float* __restrict__ W1, const float* __restrict__ b1,
         const float* __restrict__ W2, const float* __restrict__ b2,
         float* __restrict__ dst, const float* __restrict__ inv, int count)
{
    extern __shared__ char smc[];
    uint16_t* sAh  = (uint16_t*)(smc + OFF_AH);
    uint16_t* sAl  = (uint16_t*)(smc + OFF_AL);
    uint16_t* sW1h = (uint16_t*)(smc + OFF_W1H);
    uint16_t* sW1l = (uint16_t*)(smc + OFF_W1L);
    uint16_t* sW2h = (uint16_t*)(smc + OFF_W2H);
    uint16_t* sW2l = (uint16_t*)(smc + OFF_W2L);
    float*    sb1  = (float*)(smc + OFF_B1);
    float*    sb2  = (float*)(smc + OFF_B2);

    const int tid = threadIdx.x;
    const int lane = tid & 31, w = tid >> 5;
    const int g = lane >> 2, qt = lane & 3;
    const int wm = w >> 1, wn = w & 1;

    {
        int n = tid & 127, k0 = (tid >> 7) * 64;
        for (int k = k0; k < k0 + 64; k += 2) {
            uint32_t hi, lo;
            split_pair(W1[k * 128 + n], W1[(k + 1) * 128 + n], hi, lo);
            *(uint32_t*)&sW1h[n * KP + k] = hi;
            *(uint32_t*)&sW1l[n * KP + k] = lo;
        }
    }
    {
        int n = tid & 63, k0 = (tid >> 6) * 32;
        for (int k = k0; k < k0 + 32; k += 2) {
            uint32_t hi, lo;
            split_pair(W2[k * 64 + n], W2[(k + 1) * 64 + n], hi, lo);
            *(uint32_t*)&sW2h[n * KP + k] = hi;
            *(uint32_t*)&sW2l[n * KP + k] = lo;
        }
    }
    if (tid < 128) sb1[tid] = b1[tid];
    if (tid < 64)  sb2[tid] = b2[tid];
    __syncthreads();

    for (int tile = blockIdx.x; tile < NT; tile += gridDim.x) {
        const int i0 = tile * 128;
        {
            const int m = tid & 127, half = tid >> 7;
            const int gi = i0 + m;
            const bool valid = gi < count;
            const float* src;
            float scale = 1.0f;
            bool doscale = false;
            if (half == 0) {
                src = x_src + (size_t)(valid ? gi : 0) * DD;
            } else {
                src = a_src + (size_t)(valid ? gi : 0) * DD;
                scale = valid ? inv[gi] : 0.0f;
                doscale = true;
            }
            #pragma unroll
            for (int c = 0; c < 64; c += 8) {
                float4 f0 = *(const float4*)(src + c);
                float4 f1 = *(const float4*)(src + c + 4);
                if (doscale) {
                    f0.x *= scale; f0.y *= scale; f0.z *= scale; f0.w *= scale;
                    f1.x *= scale; f1.y *= scale; f1.z *= scale; f1.w *= scale;
                }
                uint32_t hw[4], lw[4];
                split_pair(f0.x, f0.y, hw[0], lw[0]);
                split_pair(f0.z, f0.w, hw[1], lw[1]);
                split_pair(f1.x, f1.y, hw[2], lw[2]);
                split_pair(f1.z, f1.w, hw[3], lw[3]);
                int e = m * KP + half * 64 + c;
                *(uint4*)&sAh[e] = *(uint4*)hw;
                *(uint4*)&sAl[e] = *(uint4*)lw;
            }
        }
        __syncthreads();

        float acc[2][8][4];
        #pragma unroll
        for (int mt = 0; mt < 2; mt++)
            #pragma unroll
            for (int nt = 0; nt < 8; nt++)
                #pragma unroll
                for (int j = 0; j < 4; j++) acc[mt][nt][j] = 0.f;

        #pragma unroll
        for (int ks = 0; ks < 8; ks++) {
            const int kb = ks * 16 + 2 * qt;
            uint32_t ah[2][4], al[2][4];
            #pragma unroll
            for (int mt = 0; mt < 2; mt++) {
                int e = (wm * 32 + mt * 16 + g) * KP + kb;
                ah[mt][0] = *(const uint32_t*)&sAh[e];
                ah[mt][1] = *(const uint32_t*)&sAh[e + 8 * KP];
                ah[mt][2] = *(const uint32_t*)&sAh[e + 8];
                ah[mt][3] = *(const uint32_t*)&sAh[e + 8 * KP + 8];
                al[mt][0] = *(const uint32_t*)&sAl[e];
                al[mt][1] = *(const uint32_t*)&sAl[e + 8 * KP];
                al[mt][2] = *(const uint32_t*)&sAl[e + 8];
                al[mt][3] = *(const uint32_t*)&sAl[e + 8 * KP + 8];
            }
            #pragma unroll
            for (int nt = 0; nt < 8; nt++) {
                int e = (wn * 64 + nt * 8 + g) * KP + kb;
                uint32_t bh[2], bl[2];
                bh[0] = *(const uint32_t*)&sW1h[e];
                bh[1] = *(const uint32_t*)&sW1h[e + 8];
                bl[0] = *(const uint32_t*)&sW1l[e];
                bl[1] = *(const uint32_t*)&sW1l[e + 8];
                mma_bf16(acc[0][nt], ah[0], bh);
                mma_bf16(acc[1][nt], ah[1], bh);
                mma_bf16(acc[0][nt], ah[0], bl);
                mma_bf16(acc[1][nt], ah[1], bl);
                mma_bf16(acc[0][nt], al[0], bh);
                mma_bf16(acc[1][nt], al[1], bh);
            }
        }
        __syncthreads();

        #pragma unroll
        for (int mt = 0; mt < 2; mt++)
            #pragma unroll
            for (int nt = 0; nt < 8; nt++) {
                int row = wm * 32 + mt * 16 + g;
                int col = wn * 64 + nt * 8 + 2 * qt;
                float v0 = fmaxf(acc[mt][nt][0] + sb1[col], 0.f);
                float v1 = fmaxf(acc[mt][nt][1] + sb1[col + 1], 0.f);
                float v2 = fmaxf(acc[mt][nt][2] + sb1[col], 0.f);
                float v3 = fmaxf(acc[mt][nt][3] + sb1[col + 1], 0.f);
                uint32_t hi, lo;
                split_pair(v0, v1, hi, lo);
                *(uint32_t*)&sAh[row * KP + col] = hi;
                *(uint32_t*)&sAl[row * KP + col] = lo;
                split_pair(v2, v3, hi, lo);
                *(uint32_t*)&sAh[(row + 8) * KP + col] = hi;
                *(uint32_t*)&sAl[(row + 8) * KP + col] = lo;
            }
        __syncthreads();

        float acc2[2][4][4];
        #pragma unroll
        for (int mt = 0; mt < 2; mt++)
            #pragma unroll
            for (int nt = 0; nt < 4; nt++)
                #pragma unroll
                for (int j = 0; j < 4; j++) acc2[mt][nt][j] = 0.f;

        #pragma unroll
        for (int ks = 0; ks < 8; ks++) {
            const int kb = ks * 16 + 2 * qt;
            uint32_t ah[2][4], al[2][4];
            #pragma unroll
            for (int mt = 0; mt < 2; mt++) {
                int e = (wm * 32 + mt * 16 + g) * KP + kb;
                ah[mt][0] = *(const uint32_t*)&sAh[e];
                ah[mt][1] = *(const uint32_t*)&sAh[e + 8 * KP];
                ah[mt][2] = *(const uint32_t*)&sAh[e + 8];
                ah[mt][3] = *(const uint32_t*)&sAh[e + 8 * KP + 8];
                al[mt][0] = *(const uint32_t*)&sAl[e];
                al[mt][1] = *(const uint32_t*)&sAl[e + 8 * KP];
                al[mt][2] = *(const uint32_t*)&sAl[e + 8];
                al[mt][3] = *(const uint32_t*)&sAl[e + 8 * KP + 8];
            }
            #pragma unroll
            for (int nt = 0; nt < 4; nt++) {
                int e = (wn * 32 + nt * 8 + g) * KP + kb;
                uint32_t bh[2], bl[2];
                bh[0] = *(const uint32_t*)&sW2h[e];
                bh[1] = *(const uint32_t*)&sW2h[e + 8];
                bl[0] = *(const uint32_t*)&sW2l[e];
                bl[1] = *(const uint32_t*)&sW2l[e + 8];
                mma_bf16(acc2[0][nt], ah[0], bh);
                mma_bf16(acc2[1][nt], ah[1], bh);
                mma_bf16(acc2[0][nt], ah[0], bl);
                mma_bf16(acc2[1][nt], ah[1], bl);
                mma_bf16(acc2[0][nt], al[0], bh);
                mma_bf16(acc2[1][nt], al[1], bh);
            }
        }

        #pragma unroll
        for (int mt = 0; mt < 2; mt++)
            #pragma unroll
            for (int nt = 0; nt < 4; nt++) {
                int rl = wm * 32 + mt * 16 + g;
                int col = wn * 32 + nt * 8 + 2 * qt;
                #pragma unroll
                for (int rh = 0; rh < 2; rh++) {
                    int row = rl + rh * 8;
                    int gi = i0 + row;
                    if (gi >= count) continue;
                    float vx = acc2[mt][nt][rh * 2 + 0] + sb2[col];
                    float vy = acc2[mt][nt][rh * 2 + 1] + sb2[col + 1];
                    float2 rv = *(const float2*)(x_src + (size_t)gi * DD + col);
                    *(float2*)(dst + (size_t)gi * DD + col) =
                        make_float2(rv.x + vx, rv.y + vy);
                }
            }
        __syncthreads();
    }
}

extern "C" void kernel_launch(void* const* d_in, const int* in_sizes, int n_in,
                              void* d_out, int out_size)
{
    const float* x   = (const float*)d_in[0];
    const float* ea  = (const float*)d_in[1];
    const float* We1 = (const float*)d_in[2];
    const float* be1 = (const float*)d_in[3];
    const float* We2 = (const float*)d_in[4];
    const float* be2 = (const float*)d_in[5];
    const float* Wn1 = (const float*)d_in[6];
    const float* bn1 = (const float*)d_in[7];
    const float* Wn2 = (const float*)d_in[8];
    const float* bn2 = (const float*)d_in[9];
    const void*  eidx = d_in[10];

    float* out_x  = (float*)d_out;
    float* out_ea = (float*)d_out + (size_t)NN * DD;

    float *agg, *inv, *Wc, *Px;
    int* cnt;
    cudaGetSymbolAddress((void**)&agg, g_agg);
    cudaGetSymbolAddress((void**)&inv, g_inv);
    cudaGetSymbolAddress((void**)&cnt, g_cnt);
    cudaGetSymbolAddress((void**)&Wc,  g_Wc);
    cudaGetSymbolAddress((void**)&Px,  g_Px);

    cudaFuncSetAttribute(edge_mma, cudaFuncAttributeMaxDynamicSharedMemorySize, E_SMEM);
    cudaFuncSetAttribute(node_mma, cudaFuncAttributeMaxDynamicSharedMemorySize, SMEMSZ);
    cudaFuncSetAttribute(px_k,     cudaFuncAttributeMaxDynamicSharedMemorySize, SMEMSZ);

    int smcount = 148;
    cudaDeviceGetAttribute(&smcount, cudaDevAttrMultiProcessorCount, 0);
    int ge = 2 * smcount < ET ? 2 * smcount : ET;
    int gn = smcount < NT ? smcount : NT;

    // Edge kernel is my 4th launch (global #6 with harness prelaunches; -s 5 window).
    prolog_k<<<(NN * DD / 4 + 255) / 256, 256>>>(eidx, agg, cnt);        // 0
    combine_w_k<<<(128 * 128 + 255) / 256, 256>>>(We1, Wc);              // 1
    px_k<<<gn, 256, SMEMSZ>>>(x, Wc, be1, Px);                           // 2
    edge_mma<<<ge, 256, E_SMEM>>>(ea, eidx, Px, Wc, We2, be2,            // 3 <- profiled
                                  out_ea, agg, ET);
    count_k<<<(EE + 255) / 256, 256>>>(eidx, cnt);                       // 4
    inv_k<<<(NN + 255) / 256, 256>>>(cnt, inv);                          // 5
    node_mma<<<gn, 256, SMEMSZ>>>(x, agg, Wn1, bn1, Wn2, bn2,            // 6
                                  out_x, inv, NN);

    // iteration 2
    zero_f4<<<(NN * DD / 4 + 255) / 256, 256>>>(agg, NN * DD / 4);
    px_k<<<gn, 256, SMEMSZ>>>(out_x, Wc, be1, Px);
    edge_mma<<<ge, 256, E_SMEM>>>(out_ea, eidx, Px, Wc, We2, be2,
                                  out_ea, agg, ET);
    node_mma<<<gn, 256, SMEMSZ>>>(out_x, agg, Wn1, bn1, Wn2, bn2,
                                  out_x, inv, NN);
}